// round 1
// baseline (speedup 1.0000x reference)
#include <cuda_runtime.h>
#include <cuda_bf16.h>

// Problem constants
#define BATCH 2
#define SEQ   2048
#define DMODEL 768
#define NHEAD 12
#define HDIM  64
#define STRIDE_ 8
#define QB    128            // queries per attention block
#define KMAX  (SEQ/STRIDE_)  // 256 strided keys max
#define KPAD  257            // padded leading dim for transposed K in smem

// Scratch (device globals — allocation-free rule)
__device__ float g_qkv[BATCH * SEQ * 3 * DMODEL];   // [B,S,3,H,HD] = [4096, 2304]
__device__ float g_attn[BATCH * SEQ * DMODEL];      // [B,S,768]

// ---------------------------------------------------------------------------
// SGEMM: C[M,N] = A[M,K] * B[N,K]^T + bias[N]
// 128x128 tile, BK=16, 256 threads, 8x8 per thread. M,N mult of 128, K mult of 16.
// ---------------------------------------------------------------------------
#define BM 128
#define BN 128
#define BK 16

__global__ __launch_bounds__(256, 2)
void sgemm_bias_kernel(const float* __restrict__ A, const float* __restrict__ B,
                       const float* __restrict__ bias, float* __restrict__ C,
                       int M, int N, int K)
{
    __shared__ float as[BK][BM];
    __shared__ float bs[BK][BN];

    const int bm = blockIdx.y * BM;
    const int bn = blockIdx.x * BN;
    const int tid = threadIdx.x;
    const int tx = tid & 15;        // 16 cols of threads
    const int ty = tid >> 4;        // 16 rows of threads

    float acc[8][8];
    #pragma unroll
    for (int r = 0; r < 8; r++)
        #pragma unroll
        for (int c = 0; c < 8; c++) acc[r][c] = 0.f;

    for (int k0 = 0; k0 < K; k0 += BK) {
        // Load A tile (128 rows x 16 k) as float4, store transposed as[k][m]
        #pragma unroll
        for (int i = 0; i < 2; i++) {
            int idx = tid + i * 256;           // 0..511
            int row = idx >> 2;
            int c4  = (idx & 3) << 2;
            float4 v = *(const float4*)&A[(bm + row) * K + k0 + c4];
            as[c4 + 0][row] = v.x;
            as[c4 + 1][row] = v.y;
            as[c4 + 2][row] = v.z;
            as[c4 + 3][row] = v.w;
        }
        // Load B tile (128 n-rows x 16 k) likewise
        #pragma unroll
        for (int i = 0; i < 2; i++) {
            int idx = tid + i * 256;
            int row = idx >> 2;
            int c4  = (idx & 3) << 2;
            float4 v = *(const float4*)&B[(bn + row) * K + k0 + c4];
            bs[c4 + 0][row] = v.x;
            bs[c4 + 1][row] = v.y;
            bs[c4 + 2][row] = v.z;
            bs[c4 + 3][row] = v.w;
        }
        __syncthreads();

        #pragma unroll
        for (int k = 0; k < BK; k++) {
            float4 a0 = *(const float4*)&as[k][ty * 8];
            float4 a1 = *(const float4*)&as[k][ty * 8 + 4];
            float4 b0 = *(const float4*)&bs[k][tx * 8];
            float4 b1 = *(const float4*)&bs[k][tx * 8 + 4];
            float ar[8] = {a0.x,a0.y,a0.z,a0.w,a1.x,a1.y,a1.z,a1.w};
            float br[8] = {b0.x,b0.y,b0.z,b0.w,b1.x,b1.y,b1.z,b1.w};
            #pragma unroll
            for (int r = 0; r < 8; r++)
                #pragma unroll
                for (int c = 0; c < 8; c++)
                    acc[r][c] += ar[r] * br[c];
        }
        __syncthreads();
    }

    // Epilogue: add bias, write float4
    #pragma unroll
    for (int r = 0; r < 8; r++) {
        int row = bm + ty * 8 + r;
        #pragma unroll
        for (int c = 0; c < 8; c += 4) {
            int col = bn + tx * 8 + c;
            float4 bv = *(const float4*)&bias[col];
            float4 o;
            o.x = acc[r][c + 0] + bv.x;
            o.y = acc[r][c + 1] + bv.y;
            o.z = acc[r][c + 2] + bv.z;
            o.w = acc[r][c + 3] + bv.w;
            *(float4*)&C[row * N + col] = o;
        }
    }
}

// ---------------------------------------------------------------------------
// Strided-mask attention.
// Mask: (j%8==0 && j<=i) || j==i || j==i-1.  Strided keys are a shared prefix
// across all queries -> stage K^T, V (strided rows) in SMEM, online softmax.
// grid: (SEQ/QB, B*H), 256 threads (8 warps x 16 queries each).
// ---------------------------------------------------------------------------
__global__ __launch_bounds__(256, 1)
void attn_kernel(const float* __restrict__ qkv, float* __restrict__ out)
{
    extern __shared__ float sm[];
    float* kT = sm;                    // [HDIM][KPAD]
    float* vS = sm + HDIM * KPAD;      // [KMAX][HDIM]
    __shared__ float sq[8][HDIM];      // one q row per warp

    const int bh = blockIdx.y;
    const int b = bh / NHEAD;
    const int h = bh % NHEAD;
    const int q0 = blockIdx.x * QB;
    int n_str = (q0 + QB - 1) / STRIDE_ + 1;   // strided keys covering this block
    if (n_str > KMAX) n_str = KMAX;

    const int tid = threadIdx.x;

    // Stage strided K (transposed) and V into SMEM.
    // idx -> (t,d): coalesced global read; kT write stride KPAD=257 (conflict-free)
    for (int idx = tid; idx < n_str * HDIM; idx += 256) {
        int t = idx >> 6;
        int d = idx & 63;
        int j = t * STRIDE_;
        int base = (b * SEQ + j) * (3 * DMODEL) + h * HDIM + d;
        kT[d * KPAD + t] = qkv[base + DMODEL];        // K
        vS[t * HDIM + d] = qkv[base + 2 * DMODEL];    // V
    }
    __syncthreads();

    const int w = tid >> 5;
    const int lane = tid & 31;
    const float scale = 0.125f;   // HD^-0.5

    for (int qq = 0; qq < QB / 8; qq++) {
        const int i = q0 + w + 8 * qq;
        const int qbase = (b * SEQ + i) * (3 * DMODEL) + h * HDIM;
        const float q_l0 = qkv[qbase + lane];
        const float q_l1 = qkv[qbase + lane + 32];
        sq[w][lane]      = q_l0;
        sq[w][lane + 32] = q_l1;
        __syncwarp();

        const int n_i = i / STRIDE_ + 1;   // strided keys valid for this query
        float m = -1e30f, lsum = 0.f, o0 = 0.f, o1 = 0.f;

        for (int t0 = 0; t0 < n_i; t0 += 32) {
            const int nb = min(32, n_i - t0);
            float s = -1e30f;
            if (lane < nb) {
                const int t = t0 + lane;
                float accd = 0.f;
                #pragma unroll
                for (int d = 0; d < HDIM; d++)
                    accd += sq[w][d] * kT[d * KPAD + t];
                s = accd * scale;
            }
            // warp max
            float bmax = s;
            #pragma unroll
            for (int off = 16; off; off >>= 1)
                bmax = fmaxf(bmax, __shfl_xor_sync(0xFFFFFFFFu, bmax, off));
            const float m_new = fmaxf(m, bmax);
            const float alpha = __expf(m - m_new);
            float p = (lane < nb) ? __expf(s - m_new) : 0.f;
            float psum = p;
            #pragma unroll
            for (int off = 16; off; off >>= 1)
                psum += __shfl_xor_sync(0xFFFFFFFFu, psum, off);
            lsum = lsum * alpha + psum;
            o0 *= alpha;
            o1 *= alpha;
            m = m_new;

            for (int jj = 0; jj < nb; jj++) {
                const float pj = __shfl_sync(0xFFFFFFFFu, p, jj);
                const float* vr = &vS[(t0 + jj) * HDIM];
                o0 += pj * vr[lane];
                o1 += pj * vr[lane + 32];
            }
        }

        // Local keys: j=i (if i%8!=0), j=i-1 (if >=0 and (i-1)%8!=0). Dedup vs strided.
        #pragma unroll
        for (int e = 0; e < 2; e++) {
            const int j = i - e;
            if (j >= 0 && (j & 7) != 0) {
                const int kb = (b * SEQ + j) * (3 * DMODEL) + h * HDIM;
                const float k0v = qkv[kb + DMODEL + lane];
                const float k1v = qkv[kb + DMODEL + lane + 32];
                float part = q_l0 * k0v + q_l1 * k1v;
                #pragma unroll
                for (int off = 16; off; off >>= 1)
                    part += __shfl_xor_sync(0xFFFFFFFFu, part, off);
                const float s = part * scale;
                const float m_new = fmaxf(m, s);
                const float alpha = __expf(m - m_new);
                const float p = __expf(s - m_new);
                lsum = lsum * alpha + p;
                o0 = o0 * alpha + p * qkv[kb + 2 * DMODEL + lane];
                o1 = o1 * alpha + p * qkv[kb + 2 * DMODEL + lane + 32];
                m = m_new;
            }
        }

        const float inv = 1.f / lsum;
        const int ob = (b * SEQ + i) * DMODEL + h * HDIM;
        out[ob + lane]      = o0 * inv;
        out[ob + lane + 32] = o1 * inv;
        __syncwarp();
    }
}

// ---------------------------------------------------------------------------
extern "C" void kernel_launch(void* const* d_in, const int* in_sizes, int n_in,
                              void* d_out, int out_size)
{
    const float* x      = (const float*)d_in[0];   // [B,S,D]
    const float* qkv_w  = (const float*)d_in[1];   // [3D, D]
    const float* qkv_b  = (const float*)d_in[2];   // [3D]
    const float* out_w  = (const float*)d_in[3];   // [D, D]
    const float* out_b  = (const float*)d_in[4];   // [D]
    float* out = (float*)d_out;                    // [B,S,D]

    float* qkv;  cudaGetSymbolAddress((void**)&qkv,  g_qkv);
    float* attn; cudaGetSymbolAddress((void**)&attn, g_attn);

    const int M = BATCH * SEQ;          // 4096
    const size_t attn_smem = (size_t)(HDIM * KPAD + KMAX * HDIM) * sizeof(float); // ~131KB
    cudaFuncSetAttribute(attn_kernel, cudaFuncAttributeMaxDynamicSharedMemorySize,
                         (int)attn_smem);

    // 1) QKV projection: [4096,768] x [2304,768]^T -> [4096,2304]
    sgemm_bias_kernel<<<dim3(3 * DMODEL / BN, M / BM), 256>>>(
        x, qkv_w, qkv_b, qkv, M, 3 * DMODEL, DMODEL);

    // 2) Strided attention -> [4096,768]
    attn_kernel<<<dim3(SEQ / QB, BATCH * NHEAD), 256, attn_smem>>>(qkv, attn);

    // 3) Output projection: [4096,768] x [768,768]^T -> [4096,768]
    sgemm_bias_kernel<<<dim3(DMODEL / BN, M / BM), 256>>>(
        attn, out_w, out_b, out, M, DMODEL, DMODEL);
}

// round 3
// speedup vs baseline: 1.8659x; 1.8659x over previous
#include <cuda_runtime.h>
#include <cuda_bf16.h>
#include <cstdint>

// ---------------- problem constants ----------------
#define BATCH 2
#define SEQ   2048
#define DMODEL 768
#define NHEAD 12
#define HDIM  64
#define STRIDE_ 8
#define QB    128
#define KMAX  (SEQ/STRIDE_)   // 256
#define KPAD  257

#define M_TOTAL (BATCH*SEQ)   // 4096
#define K_DIM   DMODEL        // 768
#define N_QKV   (3*DMODEL)    // 2304

// ---------------- device scratch ----------------
__device__ float g_qkv[M_TOTAL * N_QKV];
__device__ float g_attn[M_TOTAL * DMODEL];
__device__ __nv_bfloat16 g_ah[M_TOTAL * K_DIM];
__device__ __nv_bfloat16 g_al[M_TOTAL * K_DIM];
__device__ __nv_bfloat16 g_bh[N_QKV * K_DIM];
__device__ __nv_bfloat16 g_bl[N_QKV * K_DIM];
__device__ __nv_bfloat16 g_owh[DMODEL * K_DIM];
__device__ __nv_bfloat16 g_owl[DMODEL * K_DIM];

// ---------------- PTX helpers (portable: sm_80+) ----------------
__device__ __forceinline__ uint32_t smem_u32(const void* p) {
    uint32_t a;
    asm("{ .reg .u64 t; cvta.to.shared.u64 t, %1; cvt.u32.u64 %0, t; }" : "=r"(a) : "l"(p));
    return a;
}

#define CP_ASYNC16(dst, src) \
    asm volatile("cp.async.cg.shared.global [%0], [%1], 16;" :: "r"(dst), "l"(src))
#define CP_COMMIT() asm volatile("cp.async.commit_group;" ::: "memory")
#define CP_WAIT1() asm volatile("cp.async.wait_group 1;" ::: "memory")
#define CP_WAIT0() asm volatile("cp.async.wait_group 0;" ::: "memory")

#define LDSM_X4(r0, r1, r2, r3, addr) \
    asm volatile("ldmatrix.sync.aligned.m8n8.x4.shared.b16 {%0,%1,%2,%3}, [%4];" \
        : "=r"(r0), "=r"(r1), "=r"(r2), "=r"(r3) : "r"(addr))

#define MMA_BF16(c, a, b) \
    asm volatile("mma.sync.aligned.m16n8k16.row.col.f32.bf16.bf16.f32 " \
        "{%0,%1,%2,%3}, {%4,%5,%6,%7}, {%8,%9}, {%0,%1,%2,%3};" \
        : "+f"((c)[0]), "+f"((c)[1]), "+f"((c)[2]), "+f"((c)[3]) \
        : "r"((a)[0]), "r"((a)[1]), "r"((a)[2]), "r"((a)[3]), \
          "r"((b)[0]), "r"((b)[1]))

// ---------------- fp32 -> bf16 hi/lo split ----------------
__global__ __launch_bounds__(256)
void conv_hilo_kernel(const float* __restrict__ in, __nv_bfloat16* __restrict__ hi,
                      __nv_bfloat16* __restrict__ lo, int n4)
{
    int i = blockIdx.x * 256 + threadIdx.x;
    if (i >= n4) return;
    float4 v = ((const float4*)in)[i];
    __nv_bfloat16 h0 = __float2bfloat16(v.x);
    __nv_bfloat16 h1 = __float2bfloat16(v.y);
    __nv_bfloat16 h2 = __float2bfloat16(v.z);
    __nv_bfloat16 h3 = __float2bfloat16(v.w);
    __nv_bfloat16 l0 = __float2bfloat16(v.x - __bfloat162float(h0));
    __nv_bfloat16 l1 = __float2bfloat16(v.y - __bfloat162float(h1));
    __nv_bfloat16 l2 = __float2bfloat16(v.z - __bfloat162float(h2));
    __nv_bfloat16 l3 = __float2bfloat16(v.w - __bfloat162float(h3));
    __nv_bfloat162* hp = (__nv_bfloat162*)hi;
    __nv_bfloat162* lp = (__nv_bfloat162*)lo;
    hp[2*i]   = __nv_bfloat162(h0, h1);
    hp[2*i+1] = __nv_bfloat162(h2, h3);
    lp[2*i]   = __nv_bfloat162(l0, l1);
    lp[2*i+1] = __nv_bfloat162(l2, l3);
}

// ---------------- mma.sync GEMM ----------------
// C[M,N] = (Ah+Al)[M,768] * ((Bh+Bl)[N,768])^T + bias  (3-product hi/lo)
// 128x128x32 CTA tile, 8 warps (2 M x 4 N), warp tile 64x32.
#define GBK 32
#define NCHUNK (K_DIM / GBK)          // 24
#define TPAD 40                        // row stride in bf16 (80B: conflict-free)
#define TILE_BYTES (128 * TPAD * 2)    // 10240
#define STAGE_BYTES (4 * TILE_BYTES)   // 40960
#define GEMM_SMEM (2 * STAGE_BYTES)    // 81920

__global__ __launch_bounds__(256, 1)
void gemm_mma_kernel(const __nv_bfloat16* __restrict__ Ah, const __nv_bfloat16* __restrict__ Al,
                     const __nv_bfloat16* __restrict__ Bh, const __nv_bfloat16* __restrict__ Bl,
                     const float* __restrict__ bias, float* __restrict__ C, int N)
{
    extern __shared__ char dsm[];
    const uint32_t sbase = smem_u32(dsm);
    const int tid = threadIdx.x;
    const int lane = tid & 31;
    const int wid = tid >> 5;
    const int wm = (wid & 1) * 64;
    const int wn = (wid >> 1) * 32;
    const int bm = blockIdx.y * 128;
    const int bn = blockIdx.x * 128;

    const __nv_bfloat16* gp[4] = { Ah, Al, Bh, Bl };

    float acc[4][4][4];
    #pragma unroll
    for (int i = 0; i < 4; i++)
        #pragma unroll
        for (int j = 0; j < 4; j++)
            #pragma unroll
            for (int r = 0; r < 4; r++) acc[i][j][r] = 0.f;

    auto issue = [&](int stage, int kc) {
        const uint32_t st = sbase + (uint32_t)stage * STAGE_BYTES;
        #pragma unroll
        for (int t = 0; t < 8; ++t) {
            int task = tid + t * 256;          // 0..2047
            int tile = task >> 9;              // 0..3
            int idx  = task & 511;
            int r = idx >> 2, q = idx & 3;
            int row = (tile < 2 ? bm : bn) + r;
            uint32_t dst = st + (uint32_t)tile * TILE_BYTES + (uint32_t)(r * TPAD + q * 8) * 2;
            CP_ASYNC16(dst, gp[tile] + (size_t)row * K_DIM + kc + q * 8);
        }
        CP_COMMIT();
    };

    issue(0, 0);

    // ldmatrix lane addressing
    const int g = lane >> 3;
    const int arow = wm + (g & 1) * 8 + (lane & 7);
    const int acoff = (g >> 1) * 8;
    const int brow0 = wn + (g >> 1) * 8 + (lane & 7);
    const int bcoff = (g & 1) * 8;

    for (int c = 0; c < NCHUNK; ++c) {
        if (c + 1 < NCHUNK) { issue((c + 1) & 1, (c + 1) * GBK); CP_WAIT1(); }
        else { CP_WAIT0(); }
        __syncthreads();

        const uint32_t st = sbase + (uint32_t)(c & 1) * STAGE_BYTES;
        const uint32_t aH = st;
        const uint32_t aL = st + TILE_BYTES;
        const uint32_t bH = st + 2 * TILE_BYTES;
        const uint32_t bL = st + 3 * TILE_BYTES;

        #pragma unroll
        for (int ks = 0; ks < 2; ++ks) {
            uint32_t ah[4][4], al[4][4], bh[4][2], bl[4][2];
            const int acol = ks * 16 + acoff;
            const int bcol = ks * 16 + bcoff;
            #pragma unroll
            for (int mf = 0; mf < 4; ++mf) {
                uint32_t off = (uint32_t)((arow + mf * 16) * TPAD + acol) * 2;
                LDSM_X4(ah[mf][0], ah[mf][1], ah[mf][2], ah[mf][3], aH + off);
                LDSM_X4(al[mf][0], al[mf][1], al[mf][2], al[mf][3], aL + off);
            }
            #pragma unroll
            for (int nf2 = 0; nf2 < 2; ++nf2) {
                uint32_t off = (uint32_t)((brow0 + nf2 * 16) * TPAD + bcol) * 2;
                uint32_t r0, r1, r2, r3;
                LDSM_X4(r0, r1, r2, r3, bH + off);
                bh[2*nf2][0] = r0; bh[2*nf2][1] = r1;
                bh[2*nf2+1][0] = r2; bh[2*nf2+1][1] = r3;
                LDSM_X4(r0, r1, r2, r3, bL + off);
                bl[2*nf2][0] = r0; bl[2*nf2][1] = r1;
                bl[2*nf2+1][0] = r2; bl[2*nf2+1][1] = r3;
            }
            #pragma unroll
            for (int mf = 0; mf < 4; ++mf)
                #pragma unroll
                for (int nf = 0; nf < 4; ++nf) {
                    MMA_BF16(acc[mf][nf], ah[mf], bh[nf]);
                    MMA_BF16(acc[mf][nf], ah[mf], bl[nf]);
                    MMA_BF16(acc[mf][nf], al[mf], bh[nf]);
                }
        }
        __syncthreads();
    }

    // epilogue: c0,c1 -> (row=lane/4, n=(lane%4)*2); c2,c3 -> row+8
    #pragma unroll
    for (int mf = 0; mf < 4; ++mf) {
        const int m = bm + wm + mf * 16 + (lane >> 2);
        #pragma unroll
        for (int nf = 0; nf < 4; ++nf) {
            const int n = bn + wn + nf * 8 + (lane & 3) * 2;
            const float2 bv = *(const float2*)&bias[n];
            float2 v0 = { acc[mf][nf][0] + bv.x, acc[mf][nf][1] + bv.y };
            float2 v1 = { acc[mf][nf][2] + bv.x, acc[mf][nf][3] + bv.y };
            *(float2*)&C[(size_t)m * N + n]       = v0;
            *(float2*)&C[(size_t)(m + 8) * N + n] = v1;
        }
    }
}

// ---------------- strided-mask attention (v2: 512 thr, smem-broadcast V loop) --
__global__ __launch_bounds__(512, 1)
void attn_kernel(const float* __restrict__ qkv, float* __restrict__ out)
{
    extern __shared__ float smf[];
    float* kT = smf;                    // [HDIM][KPAD]
    float* vS = smf + HDIM * KPAD;      // [KMAX][HDIM]
    __shared__ float sq[16][HDIM];
    __shared__ float sp[16][32];

    const int bh = blockIdx.y;
    const int b = bh / NHEAD;
    const int h = bh % NHEAD;
    const int q0 = blockIdx.x * QB;
    int n_str = (q0 + QB - 1) / STRIDE_ + 1;
    if (n_str > KMAX) n_str = KMAX;
    const int n_pad = (n_str + 31) & ~31;

    const int tid = threadIdx.x;

    // stage K^T and V (float4 over d)
    for (int idx = tid; idx < n_str * 16; idx += 512) {
        const int t = idx >> 4;
        const int d4 = (idx & 15) * 4;
        const int j = t * STRIDE_;
        const float* kb = qkv + ((size_t)(b * SEQ + j)) * (3 * DMODEL) + h * HDIM;
        float4 kv = *(const float4*)(kb + DMODEL + d4);
        float4 vv = *(const float4*)(kb + 2 * DMODEL + d4);
        kT[(d4 + 0) * KPAD + t] = kv.x;
        kT[(d4 + 1) * KPAD + t] = kv.y;
        kT[(d4 + 2) * KPAD + t] = kv.z;
        kT[(d4 + 3) * KPAD + t] = kv.w;
        *(float4*)&vS[t * HDIM + d4] = vv;
    }
    // zero-fill V rows [n_str, n_pad)
    for (int idx = tid; idx < (n_pad - n_str) * 16; idx += 512) {
        const int t = n_str + (idx >> 4);
        const int d4 = (idx & 15) * 4;
        *(float4*)&vS[t * HDIM + d4] = make_float4(0.f, 0.f, 0.f, 0.f);
    }
    __syncthreads();

    const int w = tid >> 5;
    const int lane = tid & 31;
    const float scale = 0.125f;

    for (int qq = 0; qq < QB / 16; qq++) {
        const int i = q0 + w + 16 * qq;
        const size_t qbase = (size_t)(b * SEQ + i) * (3 * DMODEL) + h * HDIM;
        const float q_l0 = qkv[qbase + lane];
        const float q_l1 = qkv[qbase + lane + 32];
        sq[w][lane]      = q_l0;
        sq[w][lane + 32] = q_l1;
        __syncwarp();

        const int n_i = i / STRIDE_ + 1;
        float m = -1e30f, lsum = 0.f, o0 = 0.f, o1 = 0.f;

        for (int t0 = 0; t0 < n_i; t0 += 32) {
            const int nb = min(32, n_i - t0);
            float s = -1e30f;
            if (lane < nb) {
                const int t = t0 + lane;
                float s0 = 0.f, s1 = 0.f, s2 = 0.f, s3 = 0.f;
                #pragma unroll
                for (int d = 0; d < HDIM; d += 4) {
                    s0 += sq[w][d + 0] * kT[(d + 0) * KPAD + t];
                    s1 += sq[w][d + 1] * kT[(d + 1) * KPAD + t];
                    s2 += sq[w][d + 2] * kT[(d + 2) * KPAD + t];
                    s3 += sq[w][d + 3] * kT[(d + 3) * KPAD + t];
                }
                s = (s0 + s1 + s2 + s3) * scale;
            }
            float bmax = s;
            #pragma unroll
            for (int off = 16; off; off >>= 1)
                bmax = fmaxf(bmax, __shfl_xor_sync(0xFFFFFFFFu, bmax, off));
            const float m_new = fmaxf(m, bmax);
            const float alpha = __expf(m - m_new);
            float p = (lane < nb) ? __expf(s - m_new) : 0.f;
            float psum = p;
            #pragma unroll
            for (int off = 16; off; off >>= 1)
                psum += __shfl_xor_sync(0xFFFFFFFFu, psum, off);
            lsum = lsum * alpha + psum;
            m = m_new;

            sp[w][lane] = p;
            __syncwarp();
            float a0 = 0.f, a1 = 0.f, c0 = 0.f, c1 = 0.f;
            const float* vb = &vS[t0 * HDIM];
            #pragma unroll
            for (int jj = 0; jj < 32; jj += 2) {
                const float p0 = sp[w][jj];
                const float p1 = sp[w][jj + 1];
                a0 += p0 * vb[jj * HDIM + lane];
                a1 += p0 * vb[jj * HDIM + lane + 32];
                c0 += p1 * vb[(jj + 1) * HDIM + lane];
                c1 += p1 * vb[(jj + 1) * HDIM + lane + 32];
            }
            o0 = o0 * alpha + a0 + c0;
            o1 = o1 * alpha + a1 + c1;
            __syncwarp();
        }

        // local keys j=i, j=i-1 (skip if strided)
        #pragma unroll
        for (int e = 0; e < 2; e++) {
            const int j = i - e;
            if (j >= 0 && (j & 7) != 0) {
                const size_t kb = (size_t)(b * SEQ + j) * (3 * DMODEL) + h * HDIM;
                const float k0v = qkv[kb + DMODEL + lane];
                const float k1v = qkv[kb + DMODEL + lane + 32];
                float part = q_l0 * k0v + q_l1 * k1v;
                #pragma unroll
                for (int off = 16; off; off >>= 1)
                    part += __shfl_xor_sync(0xFFFFFFFFu, part, off);
                const float s = part * scale;
                const float m_new = fmaxf(m, s);
                const float alpha = __expf(m - m_new);
                const float p = __expf(s - m_new);
                lsum = lsum * alpha + p;
                o0 = o0 * alpha + p * qkv[kb + 2 * DMODEL + lane];
                o1 = o1 * alpha + p * qkv[kb + 2 * DMODEL + lane + 32];
                m = m_new;
            }
        }

        const float inv = 1.f / lsum;
        const size_t ob = (size_t)(b * SEQ + i) * DMODEL + h * HDIM;
        out[ob + lane]      = o0 * inv;
        out[ob + lane + 32] = o1 * inv;
        __syncwarp();
    }
}

// ---------------- launcher ----------------
extern "C" void kernel_launch(void* const* d_in, const int* in_sizes, int n_in,
                              void* d_out, int out_size)
{
    const float* x      = (const float*)d_in[0];
    const float* qkv_w  = (const float*)d_in[1];
    const float* qkv_b  = (const float*)d_in[2];
    const float* out_w  = (const float*)d_in[3];
    const float* out_b  = (const float*)d_in[4];
    float* out = (float*)d_out;

    float* qkv;  cudaGetSymbolAddress((void**)&qkv,  g_qkv);
    float* attn; cudaGetSymbolAddress((void**)&attn, g_attn);
    __nv_bfloat16 *ah, *al, *bh, *bl, *owh, *owl;
    cudaGetSymbolAddress((void**)&ah,  g_ah);
    cudaGetSymbolAddress((void**)&al,  g_al);
    cudaGetSymbolAddress((void**)&bh,  g_bh);
    cudaGetSymbolAddress((void**)&bl,  g_bl);
    cudaGetSymbolAddress((void**)&owh, g_owh);
    cudaGetSymbolAddress((void**)&owl, g_owl);

    cudaFuncSetAttribute(gemm_mma_kernel, cudaFuncAttributeMaxDynamicSharedMemorySize, GEMM_SMEM);
    const int attn_smem = (HDIM * KPAD + KMAX * HDIM) * sizeof(float);
    cudaFuncSetAttribute(attn_kernel, cudaFuncAttributeMaxDynamicSharedMemorySize, attn_smem);

    // hi/lo splits
    {
        int n4 = M_TOTAL * K_DIM / 4;
        conv_hilo_kernel<<<(n4 + 255) / 256, 256>>>(x, ah, al, n4);
        n4 = N_QKV * K_DIM / 4;
        conv_hilo_kernel<<<(n4 + 255) / 256, 256>>>(qkv_w, bh, bl, n4);
        n4 = DMODEL * K_DIM / 4;
        conv_hilo_kernel<<<(n4 + 255) / 256, 256>>>(out_w, owh, owl, n4);
    }

    // 1) QKV projection
    gemm_mma_kernel<<<dim3(N_QKV / 128, M_TOTAL / 128), 256, GEMM_SMEM>>>(
        ah, al, bh, bl, qkv_b, qkv, N_QKV);

    // 2) strided attention
    attn_kernel<<<dim3(SEQ / QB, BATCH * NHEAD), 512, attn_smem>>>(qkv, attn);

    // 3) split attention output + output projection
    {
        int n4 = M_TOTAL * K_DIM / 4;
        conv_hilo_kernel<<<(n4 + 255) / 256, 256>>>(attn, ah, al, n4);
    }
    gemm_mma_kernel<<<dim3(DMODEL / 128, M_TOTAL / 128), 256, GEMM_SMEM>>>(
        ah, al, owh, owl, out_b, out, DMODEL);
}

// round 4
// speedup vs baseline: 2.1596x; 1.1574x over previous
#include <cuda_runtime.h>
#include <cuda_bf16.h>
#include <cstdint>

// ---------------- problem constants ----------------
#define BATCH 2
#define SEQ   2048
#define DMODEL 768
#define NHEAD 12
#define HDIM  64
#define STRIDE_ 8
#define QB    128
#define KMAX  (SEQ/STRIDE_)   // 256
#define KPAD  257

#define M_TOTAL (BATCH*SEQ)   // 4096
#define K_DIM   DMODEL        // 768
#define N_QKV   (3*DMODEL)    // 2304

// ---------------- device scratch ----------------
__device__ float g_qkv[M_TOTAL * N_QKV];
__device__ __nv_bfloat16 g_ah[M_TOTAL * K_DIM];
__device__ __nv_bfloat16 g_al[M_TOTAL * K_DIM];
__device__ __nv_bfloat16 g_bh[N_QKV * K_DIM];
__device__ __nv_bfloat16 g_bl[N_QKV * K_DIM];
__device__ __nv_bfloat16 g_owh[DMODEL * K_DIM];
__device__ __nv_bfloat16 g_owl[DMODEL * K_DIM];
__device__ __nv_bfloat16 g_xh[M_TOTAL * K_DIM];
__device__ __nv_bfloat16 g_xl[M_TOTAL * K_DIM];

// ---------------- PTX helpers (portable: sm_80+) ----------------
__device__ __forceinline__ uint32_t smem_u32(const void* p) {
    uint32_t a;
    asm("{ .reg .u64 t; cvta.to.shared.u64 t, %1; cvt.u32.u64 %0, t; }" : "=r"(a) : "l"(p));
    return a;
}

#define CP_ASYNC16(dst, src) \
    asm volatile("cp.async.cg.shared.global [%0], [%1], 16;" :: "r"(dst), "l"(src))
#define CP_COMMIT() asm volatile("cp.async.commit_group;" ::: "memory")
#define CP_WAIT1() asm volatile("cp.async.wait_group 1;" ::: "memory")
#define CP_WAIT0() asm volatile("cp.async.wait_group 0;" ::: "memory")

#define LDSM_X4(r0, r1, r2, r3, addr) \
    asm volatile("ldmatrix.sync.aligned.m8n8.x4.shared.b16 {%0,%1,%2,%3}, [%4];" \
        : "=r"(r0), "=r"(r1), "=r"(r2), "=r"(r3) : "r"(addr))

#define MMA_BF16(c, a, b) \
    asm volatile("mma.sync.aligned.m16n8k16.row.col.f32.bf16.bf16.f32 " \
        "{%0,%1,%2,%3}, {%4,%5,%6,%7}, {%8,%9}, {%0,%1,%2,%3};" \
        : "+f"((c)[0]), "+f"((c)[1]), "+f"((c)[2]), "+f"((c)[3]) \
        : "r"((a)[0]), "r"((a)[1]), "r"((a)[2]), "r"((a)[3]), \
          "r"((b)[0]), "r"((b)[1]))

// ---------------- fp32 -> bf16 hi/lo split ----------------
__global__ __launch_bounds__(256)
void conv_hilo_kernel(const float* __restrict__ in, __nv_bfloat16* __restrict__ hi,
                      __nv_bfloat16* __restrict__ lo, int n4)
{
    int i = blockIdx.x * 256 + threadIdx.x;
    if (i >= n4) return;
    float4 v = ((const float4*)in)[i];
    __nv_bfloat16 h0 = __float2bfloat16(v.x);
    __nv_bfloat16 h1 = __float2bfloat16(v.y);
    __nv_bfloat16 h2 = __float2bfloat16(v.z);
    __nv_bfloat16 h3 = __float2bfloat16(v.w);
    __nv_bfloat16 l0 = __float2bfloat16(v.x - __bfloat162float(h0));
    __nv_bfloat16 l1 = __float2bfloat16(v.y - __bfloat162float(h1));
    __nv_bfloat16 l2 = __float2bfloat16(v.z - __bfloat162float(h2));
    __nv_bfloat16 l3 = __float2bfloat16(v.w - __bfloat162float(h3));
    __nv_bfloat162* hp = (__nv_bfloat162*)hi;
    __nv_bfloat162* lp = (__nv_bfloat162*)lo;
    hp[2*i]   = __nv_bfloat162(h0, h1);
    hp[2*i+1] = __nv_bfloat162(h2, h3);
    lp[2*i]   = __nv_bfloat162(l0, l1);
    lp[2*i+1] = __nv_bfloat162(l2, l3);
}

// ---------------- mma.sync GEMM (3-stage cp.async pipeline) ----------------
#define GBK 32
#define NCHUNK (K_DIM / GBK)          // 24
#define TPAD 40
#define TILE_BYTES (128 * TPAD * 2)   // 10240
#define STAGE_BYTES (4 * TILE_BYTES)  // 40960
#define GEMM_SMEM (3 * STAGE_BYTES)   // 122880

__global__ __launch_bounds__(256, 1)
void gemm_mma_kernel(const __nv_bfloat16* __restrict__ Ah, const __nv_bfloat16* __restrict__ Al,
                     const __nv_bfloat16* __restrict__ Bh, const __nv_bfloat16* __restrict__ Bl,
                     const float* __restrict__ bias, float* __restrict__ C, int N)
{
    extern __shared__ char dsm[];
    const uint32_t sbase = smem_u32(dsm);
    const int tid = threadIdx.x;
    const int lane = tid & 31;
    const int wid = tid >> 5;
    const int wm = (wid & 1) * 64;
    const int wn = (wid >> 1) * 32;
    const int bm = blockIdx.y * 128;
    const int bn = blockIdx.x * 128;

    const __nv_bfloat16* gp[4] = { Ah, Al, Bh, Bl };

    float acc[4][4][4];
    #pragma unroll
    for (int i = 0; i < 4; i++)
        #pragma unroll
        for (int j = 0; j < 4; j++)
            #pragma unroll
            for (int r = 0; r < 4; r++) acc[i][j][r] = 0.f;

    auto issue = [&](int stage, int kc) {
        const uint32_t st = sbase + (uint32_t)stage * STAGE_BYTES;
        #pragma unroll
        for (int t = 0; t < 8; ++t) {
            int task = tid + t * 256;
            int tile = task >> 9;
            int idx  = task & 511;
            int r = idx >> 2, q = idx & 3;
            int row = (tile < 2 ? bm : bn) + r;
            uint32_t dst = st + (uint32_t)tile * TILE_BYTES + (uint32_t)(r * TPAD + q * 8) * 2;
            CP_ASYNC16(dst, gp[tile] + (size_t)row * K_DIM + kc + q * 8);
        }
        CP_COMMIT();
    };

    issue(0, 0);
    issue(1, GBK);

    const int g = lane >> 3;
    const int arow = wm + (g & 1) * 8 + (lane & 7);
    const int acoff = (g >> 1) * 8;
    const int brow0 = wn + (g >> 1) * 8 + (lane & 7);
    const int bcoff = (g & 1) * 8;

    for (int c = 0; c < NCHUNK; ++c) {
        if (c + 1 < NCHUNK) { CP_WAIT1(); } else { CP_WAIT0(); }
        __syncthreads();
        if (c + 2 < NCHUNK) issue((c + 2) % 3, (c + 2) * GBK);

        const uint32_t st = sbase + (uint32_t)(c % 3) * STAGE_BYTES;
        const uint32_t aH = st;
        const uint32_t aL = st + TILE_BYTES;
        const uint32_t bH = st + 2 * TILE_BYTES;
        const uint32_t bL = st + 3 * TILE_BYTES;

        #pragma unroll
        for (int ks = 0; ks < 2; ++ks) {
            uint32_t ah[4][4], al[4][4], bh[4][2], bl[4][2];
            const int acol = ks * 16 + acoff;
            const int bcol = ks * 16 + bcoff;
            #pragma unroll
            for (int mf = 0; mf < 4; ++mf) {
                uint32_t off = (uint32_t)((arow + mf * 16) * TPAD + acol) * 2;
                LDSM_X4(ah[mf][0], ah[mf][1], ah[mf][2], ah[mf][3], aH + off);
                LDSM_X4(al[mf][0], al[mf][1], al[mf][2], al[mf][3], aL + off);
            }
            #pragma unroll
            for (int nf2 = 0; nf2 < 2; ++nf2) {
                uint32_t off = (uint32_t)((brow0 + nf2 * 16) * TPAD + bcol) * 2;
                uint32_t r0, r1, r2, r3;
                LDSM_X4(r0, r1, r2, r3, bH + off);
                bh[2*nf2][0] = r0; bh[2*nf2][1] = r1;
                bh[2*nf2+1][0] = r2; bh[2*nf2+1][1] = r3;
                LDSM_X4(r0, r1, r2, r3, bL + off);
                bl[2*nf2][0] = r0; bl[2*nf2][1] = r1;
                bl[2*nf2+1][0] = r2; bl[2*nf2+1][1] = r3;
            }
            #pragma unroll
            for (int mf = 0; mf < 4; ++mf)
                #pragma unroll
                for (int nf = 0; nf < 4; ++nf) {
                    MMA_BF16(acc[mf][nf], ah[mf], bh[nf]);
                    MMA_BF16(acc[mf][nf], ah[mf], bl[nf]);
                    MMA_BF16(acc[mf][nf], al[mf], bh[nf]);
                }
        }
        // no trailing sync: next iter's head sync protects slot reuse
    }

    #pragma unroll
    for (int mf = 0; mf < 4; ++mf) {
        const int m = bm + wm + mf * 16 + (lane >> 2);
        #pragma unroll
        for (int nf = 0; nf < 4; ++nf) {
            const int n = bn + wn + nf * 8 + (lane & 3) * 2;
            const float2 bv = *(const float2*)&bias[n];
            float2 v0 = { acc[mf][nf][0] + bv.x, acc[mf][nf][1] + bv.y };
            float2 v1 = { acc[mf][nf][2] + bv.x, acc[mf][nf][3] + bv.y };
            *(float2*)&C[(size_t)m * N + n]       = v0;
            *(float2*)&C[(size_t)(m + 8) * N + n] = v1;
        }
    }
}

// ---------------- strided attention v3: 2 queries/warp, vectorized ----------
// Writes bf16 hi/lo directly (feeds output projection).
__global__ __launch_bounds__(512, 1)
void attn_kernel(const float* __restrict__ qkv,
                 __nv_bfloat16* __restrict__ oh, __nv_bfloat16* __restrict__ ol)
{
    extern __shared__ float smf[];
    float* kT = smf;                    // [HDIM][KPAD]
    float* vS = smf + HDIM * KPAD;      // [n_pad][HDIM]
    __shared__ float sq[32][HDIM];
    __shared__ float sp[32][32];

    const int bh = blockIdx.y;
    const int b = bh / NHEAD;
    const int h = bh % NHEAD;
    const int q0 = blockIdx.x * QB;
    int n_str = (q0 + QB - 1) / STRIDE_ + 1;
    if (n_str > KMAX) n_str = KMAX;
    const int n_pad = (n_str + 31) & ~31;

    const int tid = threadIdx.x;

    // stage K^T and V
    for (int idx = tid; idx < n_str * 16; idx += 512) {
        const int t = idx >> 4;
        const int d4 = (idx & 15) * 4;
        const int j = t * STRIDE_;
        const float* kb = qkv + ((size_t)(b * SEQ + j)) * (3 * DMODEL) + h * HDIM;
        float4 kv = *(const float4*)(kb + DMODEL + d4);
        float4 vv = *(const float4*)(kb + 2 * DMODEL + d4);
        kT[(d4 + 0) * KPAD + t] = kv.x;
        kT[(d4 + 1) * KPAD + t] = kv.y;
        kT[(d4 + 2) * KPAD + t] = kv.z;
        kT[(d4 + 3) * KPAD + t] = kv.w;
        *(float4*)&vS[t * HDIM + d4] = vv;
    }
    // zero-pad rows [n_str, n_pad) of V and K^T
    for (int idx = tid; idx < (n_pad - n_str) * 16; idx += 512) {
        const int t = n_str + (idx >> 4);
        const int d4 = (idx & 15) * 4;
        *(float4*)&vS[t * HDIM + d4] = make_float4(0.f, 0.f, 0.f, 0.f);
        kT[(d4 + 0) * KPAD + t] = 0.f;
        kT[(d4 + 1) * KPAD + t] = 0.f;
        kT[(d4 + 2) * KPAD + t] = 0.f;
        kT[(d4 + 3) * KPAD + t] = 0.f;
    }
    __syncthreads();

    const int w = tid >> 5;
    const int lane = tid & 31;
    const float scale = 0.125f;

    for (int pass = 0; pass < 4; ++pass) {
        const int ia = q0 + pass * 32 + w;       // query A
        const int ib = ia + 16;                  // query B
        const size_t qba = (size_t)(b * SEQ + ia) * (3 * DMODEL) + h * HDIM;
        const size_t qbb = (size_t)(b * SEQ + ib) * (3 * DMODEL) + h * HDIM;
        const float qa0 = qkv[qba + lane], qa1 = qkv[qba + lane + 32];
        const float qb0 = qkv[qbb + lane], qb1 = qkv[qbb + lane + 32];
        sq[w][lane] = qa0;       sq[w][lane + 32] = qa1;
        sq[w + 16][lane] = qb0;  sq[w + 16][lane + 32] = qb1;
        __syncwarp();

        const int n_a = ia / STRIDE_ + 1;
        const int n_b = ib / STRIDE_ + 1;     // n_b >= n_a, n_b <= n_str
        float ma = -1e30f, mb = -1e30f, la = 0.f, lb = 0.f;
        float oa0 = 0.f, oa1 = 0.f, ob0 = 0.f, ob1 = 0.f;

        for (int t0 = 0; t0 < n_b; t0 += 32) {
            const int t = t0 + lane;
            float da = 0.f, db = 0.f;
            #pragma unroll
            for (int d = 0; d < HDIM; d += 4) {
                const float4 a4 = *(const float4*)&sq[w][d];
                const float4 b4 = *(const float4*)&sq[w + 16][d];
                const float k0 = kT[(d + 0) * KPAD + t];
                const float k1 = kT[(d + 1) * KPAD + t];
                const float k2 = kT[(d + 2) * KPAD + t];
                const float k3 = kT[(d + 3) * KPAD + t];
                da += a4.x * k0 + a4.y * k1 + a4.z * k2 + a4.w * k3;
                db += b4.x * k0 + b4.y * k1 + b4.z * k2 + b4.w * k3;
            }
            const float sa = (t < n_a) ? da * scale : -1e30f;
            const float sb = (t < n_b) ? db * scale : -1e30f;

            float mxa = sa, mxb = sb;
            #pragma unroll
            for (int off = 16; off; off >>= 1) {
                mxa = fmaxf(mxa, __shfl_xor_sync(0xFFFFFFFFu, mxa, off));
                mxb = fmaxf(mxb, __shfl_xor_sync(0xFFFFFFFFu, mxb, off));
            }
            const float mna = fmaxf(ma, mxa);
            const float mnb = fmaxf(mb, mxb);
            const float ala = __expf(ma - mna);
            const float alb = __expf(mb - mnb);
            float pa = __expf(sa - mna);
            float pb = __expf(sb - mnb);
            float sua = pa, sub = pb;
            #pragma unroll
            for (int off = 16; off; off >>= 1) {
                sua += __shfl_xor_sync(0xFFFFFFFFu, sua, off);
                sub += __shfl_xor_sync(0xFFFFFFFFu, sub, off);
            }
            la = la * ala + sua;
            lb = lb * alb + sub;
            ma = mna;
            mb = mnb;

            sp[w][lane] = pa;
            sp[w + 16][lane] = pb;
            __syncwarp();

            float a0 = 0.f, a1 = 0.f, b0 = 0.f, b1 = 0.f;
            const float* vb = &vS[(size_t)t0 * HDIM + 2 * lane];
            #pragma unroll
            for (int j4 = 0; j4 < 32; j4 += 4) {
                const float4 p4a = *(const float4*)&sp[w][j4];
                const float4 p4b = *(const float4*)&sp[w + 16][j4];
                const float2 v0 = *(const float2*)&vb[(j4 + 0) * HDIM];
                const float2 v1 = *(const float2*)&vb[(j4 + 1) * HDIM];
                const float2 v2 = *(const float2*)&vb[(j4 + 2) * HDIM];
                const float2 v3 = *(const float2*)&vb[(j4 + 3) * HDIM];
                a0 += p4a.x * v0.x + p4a.y * v1.x + p4a.z * v2.x + p4a.w * v3.x;
                a1 += p4a.x * v0.y + p4a.y * v1.y + p4a.z * v2.y + p4a.w * v3.y;
                b0 += p4b.x * v0.x + p4b.y * v1.x + p4b.z * v2.x + p4b.w * v3.x;
                b1 += p4b.x * v0.y + p4b.y * v1.y + p4b.z * v2.y + p4b.w * v3.y;
            }
            oa0 = oa0 * ala + a0;
            oa1 = oa1 * ala + a1;
            ob0 = ob0 * alb + b0;
            ob1 = ob1 * alb + b1;
            __syncwarp();
        }

        // local keys j=i, j=i-1 (skip strided dupes), per query
        #pragma unroll
        for (int sel = 0; sel < 2; ++sel) {
            const int i = sel ? ib : ia;
            const float q0r = sel ? qb0 : qa0;
            const float q1r = sel ? qb1 : qa1;
            float& m_ = sel ? mb : ma;
            float& l_ = sel ? lb : la;
            float& x0 = sel ? ob0 : oa0;
            float& x1 = sel ? ob1 : oa1;
            #pragma unroll
            for (int e = 0; e < 2; e++) {
                const int j = i - e;
                if (j >= 0 && (j & 7) != 0) {
                    const size_t kb = (size_t)(b * SEQ + j) * (3 * DMODEL) + h * HDIM;
                    float part = q0r * qkv[kb + DMODEL + lane] + q1r * qkv[kb + DMODEL + lane + 32];
                    #pragma unroll
                    for (int off = 16; off; off >>= 1)
                        part += __shfl_xor_sync(0xFFFFFFFFu, part, off);
                    const float s = part * scale;
                    const float mn = fmaxf(m_, s);
                    const float al = __expf(m_ - mn);
                    const float p = __expf(s - mn);
                    const float2 vv = *(const float2*)&qkv[kb + 2 * DMODEL + 2 * lane];
                    l_ = l_ * al + p;
                    x0 = x0 * al + p * vv.x;
                    x1 = x1 * al + p * vv.y;
                    m_ = mn;
                }
            }
        }

        // normalize, split hi/lo, write bf16
        {
            const float iva = 1.f / la, ivb = 1.f / lb;
            const float fa0 = oa0 * iva, fa1 = oa1 * iva;
            const float fb0 = ob0 * ivb, fb1 = ob1 * ivb;
            const size_t oba = (size_t)(b * SEQ + ia) * DMODEL + h * HDIM + 2 * lane;
            const size_t obb = (size_t)(b * SEQ + ib) * DMODEL + h * HDIM + 2 * lane;
            __nv_bfloat16 h0 = __float2bfloat16(fa0), h1 = __float2bfloat16(fa1);
            *(__nv_bfloat162*)&oh[oba] = __nv_bfloat162(h0, h1);
            *(__nv_bfloat162*)&ol[oba] = __nv_bfloat162(
                __float2bfloat16(fa0 - __bfloat162float(h0)),
                __float2bfloat16(fa1 - __bfloat162float(h1)));
            h0 = __float2bfloat16(fb0); h1 = __float2bfloat16(fb1);
            *(__nv_bfloat162*)&oh[obb] = __nv_bfloat162(h0, h1);
            *(__nv_bfloat162*)&ol[obb] = __nv_bfloat162(
                __float2bfloat16(fb0 - __bfloat162float(h0)),
                __float2bfloat16(fb1 - __bfloat162float(h1)));
        }
        __syncwarp();
    }
}

// ---------------- launcher ----------------
extern "C" void kernel_launch(void* const* d_in, const int* in_sizes, int n_in,
                              void* d_out, int out_size)
{
    const float* x      = (const float*)d_in[0];
    const float* qkv_w  = (const float*)d_in[1];
    const float* qkv_b  = (const float*)d_in[2];
    const float* out_w  = (const float*)d_in[3];
    const float* out_b  = (const float*)d_in[4];
    float* out = (float*)d_out;

    float* qkv; cudaGetSymbolAddress((void**)&qkv, g_qkv);
    __nv_bfloat16 *ah, *al, *bh, *bl, *owh, *owl, *xh, *xl;
    cudaGetSymbolAddress((void**)&ah,  g_ah);
    cudaGetSymbolAddress((void**)&al,  g_al);
    cudaGetSymbolAddress((void**)&bh,  g_bh);
    cudaGetSymbolAddress((void**)&bl,  g_bl);
    cudaGetSymbolAddress((void**)&owh, g_owh);
    cudaGetSymbolAddress((void**)&owl, g_owl);
    cudaGetSymbolAddress((void**)&xh,  g_xh);
    cudaGetSymbolAddress((void**)&xl,  g_xl);

    cudaFuncSetAttribute(gemm_mma_kernel, cudaFuncAttributeMaxDynamicSharedMemorySize, GEMM_SMEM);
    const int attn_smem = (HDIM * KPAD + KMAX * HDIM) * sizeof(float);
    cudaFuncSetAttribute(attn_kernel, cudaFuncAttributeMaxDynamicSharedMemorySize, attn_smem);

    // hi/lo splits of x and weights
    {
        int n4 = M_TOTAL * K_DIM / 4;
        conv_hilo_kernel<<<(n4 + 255) / 256, 256>>>(x, xh, xl, n4);
        n4 = N_QKV * K_DIM / 4;
        conv_hilo_kernel<<<(n4 + 255) / 256, 256>>>(qkv_w, bh, bl, n4);
        n4 = DMODEL * K_DIM / 4;
        conv_hilo_kernel<<<(n4 + 255) / 256, 256>>>(out_w, owh, owl, n4);
    }

    // 1) QKV projection
    gemm_mma_kernel<<<dim3(N_QKV / 128, M_TOTAL / 128), 256, GEMM_SMEM>>>(
        xh, xl, bh, bl, qkv_b, qkv, N_QKV);

    // 2) strided attention (writes bf16 hi/lo directly)
    attn_kernel<<<dim3(SEQ / QB, BATCH * NHEAD), 512, attn_smem>>>(qkv, ah, al);

    // 3) output projection
    gemm_mma_kernel<<<dim3(DMODEL / 128, M_TOTAL / 128), 256, GEMM_SMEM>>>(
        ah, al, owh, owl, out_b, out, DMODEL);
}

// round 5
// speedup vs baseline: 2.2402x; 1.0373x over previous
#include <cuda_runtime.h>
#include <cuda_bf16.h>
#include <cstdint>

// ---------------- problem constants ----------------
#define BATCH 2
#define SEQ   2048
#define DMODEL 768
#define NHEAD 12
#define HDIM  64
#define STRIDE_ 8
#define QB    128
#define KMAX  (SEQ/STRIDE_)   // 256
#define KPAD  257

#define M_TOTAL (BATCH*SEQ)   // 4096
#define K_DIM   DMODEL        // 768
#define N_QKV   (3*DMODEL)    // 2304

// ---------------- device scratch ----------------
__device__ float g_qkv[M_TOTAL * N_QKV];
__device__ __nv_bfloat16 g_ah[M_TOTAL * K_DIM];
__device__ __nv_bfloat16 g_al[M_TOTAL * K_DIM];
__device__ __nv_bfloat16 g_bh[N_QKV * K_DIM];
__device__ __nv_bfloat16 g_bl[N_QKV * K_DIM];
__device__ __nv_bfloat16 g_owh[DMODEL * K_DIM];
__device__ __nv_bfloat16 g_owl[DMODEL * K_DIM];
__device__ __nv_bfloat16 g_xh[M_TOTAL * K_DIM];
__device__ __nv_bfloat16 g_xl[M_TOTAL * K_DIM];

// ---------------- PTX helpers (portable: sm_80+) ----------------
__device__ __forceinline__ uint32_t smem_u32(const void* p) {
    uint32_t a;
    asm("{ .reg .u64 t; cvta.to.shared.u64 t, %1; cvt.u32.u64 %0, t; }" : "=r"(a) : "l"(p));
    return a;
}

#define CP_ASYNC16(dst, src) \
    asm volatile("cp.async.cg.shared.global [%0], [%1], 16;" :: "r"(dst), "l"(src))
#define CP_COMMIT() asm volatile("cp.async.commit_group;" ::: "memory")
#define CP_WAIT1() asm volatile("cp.async.wait_group 1;" ::: "memory")
#define CP_WAIT0() asm volatile("cp.async.wait_group 0;" ::: "memory")

#define LDSM_X4(r0, r1, r2, r3, addr) \
    asm volatile("ldmatrix.sync.aligned.m8n8.x4.shared.b16 {%0,%1,%2,%3}, [%4];" \
        : "=r"(r0), "=r"(r1), "=r"(r2), "=r"(r3) : "r"(addr))

#define MMA_BF16(c, a, b) \
    asm volatile("mma.sync.aligned.m16n8k16.row.col.f32.bf16.bf16.f32 " \
        "{%0,%1,%2,%3}, {%4,%5,%6,%7}, {%8,%9}, {%0,%1,%2,%3};" \
        : "+f"((c)[0]), "+f"((c)[1]), "+f"((c)[2]), "+f"((c)[3]) \
        : "r"((a)[0]), "r"((a)[1]), "r"((a)[2]), "r"((a)[3]), \
          "r"((b)[0]), "r"((b)[1]))

// ---------------- fp32 -> bf16 hi/lo split ----------------
__global__ __launch_bounds__(256)
void conv_hilo_kernel(const float* __restrict__ in, __nv_bfloat16* __restrict__ hi,
                      __nv_bfloat16* __restrict__ lo, int n4)
{
    int i = blockIdx.x * 256 + threadIdx.x;
    if (i >= n4) return;
    float4 v = ((const float4*)in)[i];
    __nv_bfloat16 h0 = __float2bfloat16(v.x);
    __nv_bfloat16 h1 = __float2bfloat16(v.y);
    __nv_bfloat16 h2 = __float2bfloat16(v.z);
    __nv_bfloat16 h3 = __float2bfloat16(v.w);
    __nv_bfloat16 l0 = __float2bfloat16(v.x - __bfloat162float(h0));
    __nv_bfloat16 l1 = __float2bfloat16(v.y - __bfloat162float(h1));
    __nv_bfloat16 l2 = __float2bfloat16(v.z - __bfloat162float(h2));
    __nv_bfloat16 l3 = __float2bfloat16(v.w - __bfloat162float(h3));
    __nv_bfloat162* hp = (__nv_bfloat162*)hi;
    __nv_bfloat162* lp = (__nv_bfloat162*)lo;
    hp[2*i]   = __nv_bfloat162(h0, h1);
    hp[2*i+1] = __nv_bfloat162(h2, h3);
    lp[2*i]   = __nv_bfloat162(l0, l1);
    lp[2*i+1] = __nv_bfloat162(l2, l3);
}

#define GBK 32
#define NCHUNK (K_DIM / GBK)          // 24
#define TPAD 40

// ============ GEMM A: 256x128 CTA tile, 8 warps of 64x64 (QKV) =============
#define A2_TILE  (256 * TPAD * 2)     // 20480 B (Ah or Al)
#define B2_TILE  (128 * TPAD * 2)     // 10240 B (Bh or Bl)
#define STAGE2   (2 * A2_TILE + 2 * B2_TILE)   // 61440
#define GEMM2_SMEM (3 * STAGE2)                // 184320

__global__ __launch_bounds__(256, 1)
void gemm_mma256_kernel(const __nv_bfloat16* __restrict__ Ah, const __nv_bfloat16* __restrict__ Al,
                        const __nv_bfloat16* __restrict__ Bh, const __nv_bfloat16* __restrict__ Bl,
                        const float* __restrict__ bias, float* __restrict__ C, int N)
{
    extern __shared__ char dsm[];
    const uint32_t sbase = smem_u32(dsm);
    const int tid = threadIdx.x;
    const int lane = tid & 31;
    const int wid = tid >> 5;
    const int wm = (wid & 3) * 64;       // 4 M groups
    const int wn = (wid >> 2) * 64;      // 2 N groups
    const int bm = blockIdx.y * 256;
    const int bn = blockIdx.x * 128;

    float acc[4][8][4];
    #pragma unroll
    for (int i = 0; i < 4; i++)
        #pragma unroll
        for (int j = 0; j < 8; j++)
            #pragma unroll
            for (int r = 0; r < 4; r++) acc[i][j][r] = 0.f;

    // stage-relative tile offsets
    const uint32_t OFF_AH = 0, OFF_AL = A2_TILE, OFF_BH = 2 * A2_TILE,
                   OFF_BL = 2 * A2_TILE + B2_TILE;

    auto issue = [&](int stage, int kc) {
        const uint32_t st = sbase + (uint32_t)stage * STAGE2;
        #pragma unroll
        for (int t = 0; t < 12; ++t) {
            const int task = tid + t * 256;        // 0..3071
            int tile, idx;
            if (task < 1024)      { tile = 0; idx = task; }
            else if (task < 2048) { tile = 1; idx = task - 1024; }
            else if (task < 2560) { tile = 2; idx = task - 2048; }
            else                  { tile = 3; idx = task - 2560; }
            const int r = idx >> 2, q = idx & 3;
            const uint32_t toff = (tile == 0) ? OFF_AH : (tile == 1) ? OFF_AL
                                : (tile == 2) ? OFF_BH : OFF_BL;
            const __nv_bfloat16* src = (tile == 0) ? Ah : (tile == 1) ? Al
                                      : (tile == 2) ? Bh : Bl;
            const int row = ((tile < 2) ? bm : bn) + r;
            uint32_t dst = st + toff + (uint32_t)(r * TPAD + q * 8) * 2;
            CP_ASYNC16(dst, src + (size_t)row * K_DIM + kc + q * 8);
        }
        CP_COMMIT();
    };

    issue(0, 0);
    issue(1, GBK);

    const int g = lane >> 3;
    const int arow = wm + (g & 1) * 8 + (lane & 7);
    const int acoff = (g >> 1) * 8;
    const int brow0 = wn + (g >> 1) * 8 + (lane & 7);
    const int bcoff = (g & 1) * 8;

    for (int c = 0; c < NCHUNK; ++c) {
        if (c + 1 < NCHUNK) { CP_WAIT1(); } else { CP_WAIT0(); }
        __syncthreads();
        if (c + 2 < NCHUNK) issue((c + 2) % 3, (c + 2) * GBK);

        const uint32_t st = sbase + (uint32_t)(c % 3) * STAGE2;
        const uint32_t aH = st + OFF_AH;
        const uint32_t aL = st + OFF_AL;
        const uint32_t bH = st + OFF_BH;
        const uint32_t bL = st + OFF_BL;

        #pragma unroll
        for (int ks = 0; ks < 2; ++ks) {
            uint32_t ah[4][4], al[4][4], bh[8][2], bl[8][2];
            const int acol = ks * 16 + acoff;
            const int bcol = ks * 16 + bcoff;
            #pragma unroll
            for (int mf = 0; mf < 4; ++mf) {
                uint32_t off = (uint32_t)((arow + mf * 16) * TPAD + acol) * 2;
                LDSM_X4(ah[mf][0], ah[mf][1], ah[mf][2], ah[mf][3], aH + off);
                LDSM_X4(al[mf][0], al[mf][1], al[mf][2], al[mf][3], aL + off);
            }
            #pragma unroll
            for (int nf2 = 0; nf2 < 4; ++nf2) {
                uint32_t off = (uint32_t)((brow0 + nf2 * 16) * TPAD + bcol) * 2;
                uint32_t r0, r1, r2, r3;
                LDSM_X4(r0, r1, r2, r3, bH + off);
                bh[2*nf2][0] = r0; bh[2*nf2][1] = r1;
                bh[2*nf2+1][0] = r2; bh[2*nf2+1][1] = r3;
                LDSM_X4(r0, r1, r2, r3, bL + off);
                bl[2*nf2][0] = r0; bl[2*nf2][1] = r1;
                bl[2*nf2+1][0] = r2; bl[2*nf2+1][1] = r3;
            }
            #pragma unroll
            for (int mf = 0; mf < 4; ++mf)
                #pragma unroll
                for (int nf = 0; nf < 8; ++nf) {
                    MMA_BF16(acc[mf][nf], ah[mf], bh[nf]);
                    MMA_BF16(acc[mf][nf], ah[mf], bl[nf]);
                    MMA_BF16(acc[mf][nf], al[mf], bh[nf]);
                }
        }
    }

    #pragma unroll
    for (int mf = 0; mf < 4; ++mf) {
        const int m = bm + wm + mf * 16 + (lane >> 2);
        #pragma unroll
        for (int nf = 0; nf < 8; ++nf) {
            const int n = bn + wn + nf * 8 + (lane & 3) * 2;
            const float2 bv = *(const float2*)&bias[n];
            float2 v0 = { acc[mf][nf][0] + bv.x, acc[mf][nf][1] + bv.y };
            float2 v1 = { acc[mf][nf][2] + bv.x, acc[mf][nf][3] + bv.y };
            *(float2*)&C[(size_t)m * N + n]       = v0;
            *(float2*)&C[(size_t)(m + 8) * N + n] = v1;
        }
    }
}

// ============ GEMM B: 128x128 CTA tile, 8 warps of 64x32 (proj) ============
#define TILE_BYTES (128 * TPAD * 2)   // 10240
#define STAGE_BYTES (4 * TILE_BYTES)  // 40960
#define GEMM_SMEM (3 * STAGE_BYTES)   // 122880

__global__ __launch_bounds__(256, 1)
void gemm_mma_kernel(const __nv_bfloat16* __restrict__ Ah, const __nv_bfloat16* __restrict__ Al,
                     const __nv_bfloat16* __restrict__ Bh, const __nv_bfloat16* __restrict__ Bl,
                     const float* __restrict__ bias, float* __restrict__ C, int N)
{
    extern __shared__ char dsm[];
    const uint32_t sbase = smem_u32(dsm);
    const int tid = threadIdx.x;
    const int lane = tid & 31;
    const int wid = tid >> 5;
    const int wm = (wid & 1) * 64;
    const int wn = (wid >> 1) * 32;
    const int bm = blockIdx.y * 128;
    const int bn = blockIdx.x * 128;

    const __nv_bfloat16* gp[4] = { Ah, Al, Bh, Bl };

    float acc[4][4][4];
    #pragma unroll
    for (int i = 0; i < 4; i++)
        #pragma unroll
        for (int j = 0; j < 4; j++)
            #pragma unroll
            for (int r = 0; r < 4; r++) acc[i][j][r] = 0.f;

    auto issue = [&](int stage, int kc) {
        const uint32_t st = sbase + (uint32_t)stage * STAGE_BYTES;
        #pragma unroll
        for (int t = 0; t < 8; ++t) {
            int task = tid + t * 256;
            int tile = task >> 9;
            int idx  = task & 511;
            int r = idx >> 2, q = idx & 3;
            int row = (tile < 2 ? bm : bn) + r;
            uint32_t dst = st + (uint32_t)tile * TILE_BYTES + (uint32_t)(r * TPAD + q * 8) * 2;
            CP_ASYNC16(dst, gp[tile] + (size_t)row * K_DIM + kc + q * 8);
        }
        CP_COMMIT();
    };

    issue(0, 0);
    issue(1, GBK);

    const int g = lane >> 3;
    const int arow = wm + (g & 1) * 8 + (lane & 7);
    const int acoff = (g >> 1) * 8;
    const int brow0 = wn + (g >> 1) * 8 + (lane & 7);
    const int bcoff = (g & 1) * 8;

    for (int c = 0; c < NCHUNK; ++c) {
        if (c + 1 < NCHUNK) { CP_WAIT1(); } else { CP_WAIT0(); }
        __syncthreads();
        if (c + 2 < NCHUNK) issue((c + 2) % 3, (c + 2) * GBK);

        const uint32_t st = sbase + (uint32_t)(c % 3) * STAGE_BYTES;
        const uint32_t aH = st;
        const uint32_t aL = st + TILE_BYTES;
        const uint32_t bH = st + 2 * TILE_BYTES;
        const uint32_t bL = st + 3 * TILE_BYTES;

        #pragma unroll
        for (int ks = 0; ks < 2; ++ks) {
            uint32_t ah[4][4], al[4][4], bh[4][2], bl[4][2];
            const int acol = ks * 16 + acoff;
            const int bcol = ks * 16 + bcoff;
            #pragma unroll
            for (int mf = 0; mf < 4; ++mf) {
                uint32_t off = (uint32_t)((arow + mf * 16) * TPAD + acol) * 2;
                LDSM_X4(ah[mf][0], ah[mf][1], ah[mf][2], ah[mf][3], aH + off);
                LDSM_X4(al[mf][0], al[mf][1], al[mf][2], al[mf][3], aL + off);
            }
            #pragma unroll
            for (int nf2 = 0; nf2 < 2; ++nf2) {
                uint32_t off = (uint32_t)((brow0 + nf2 * 16) * TPAD + bcol) * 2;
                uint32_t r0, r1, r2, r3;
                LDSM_X4(r0, r1, r2, r3, bH + off);
                bh[2*nf2][0] = r0; bh[2*nf2][1] = r1;
                bh[2*nf2+1][0] = r2; bh[2*nf2+1][1] = r3;
                LDSM_X4(r0, r1, r2, r3, bL + off);
                bl[2*nf2][0] = r0; bl[2*nf2][1] = r1;
                bl[2*nf2+1][0] = r2; bl[2*nf2+1][1] = r3;
            }
            #pragma unroll
            for (int mf = 0; mf < 4; ++mf)
                #pragma unroll
                for (int nf = 0; nf < 4; ++nf) {
                    MMA_BF16(acc[mf][nf], ah[mf], bh[nf]);
                    MMA_BF16(acc[mf][nf], ah[mf], bl[nf]);
                    MMA_BF16(acc[mf][nf], al[mf], bh[nf]);
                }
        }
    }

    #pragma unroll
    for (int mf = 0; mf < 4; ++mf) {
        const int m = bm + wm + mf * 16 + (lane >> 2);
        #pragma unroll
        for (int nf = 0; nf < 4; ++nf) {
            const int n = bn + wn + nf * 8 + (lane & 3) * 2;
            const float2 bv = *(const float2*)&bias[n];
            float2 v0 = { acc[mf][nf][0] + bv.x, acc[mf][nf][1] + bv.y };
            float2 v1 = { acc[mf][nf][2] + bv.x, acc[mf][nf][3] + bv.y };
            *(float2*)&C[(size_t)m * N + n]       = v0;
            *(float2*)&C[(size_t)(m + 8) * N + n] = v1;
        }
    }
}

// ---------------- strided attention: 2 queries/warp, vectorized -------------
__global__ __launch_bounds__(512, 1)
void attn_kernel(const float* __restrict__ qkv,
                 __nv_bfloat16* __restrict__ oh, __nv_bfloat16* __restrict__ ol)
{
    extern __shared__ float smf[];
    float* kT = smf;                    // [HDIM][KPAD]
    float* vS = smf + HDIM * KPAD;      // [n_pad][HDIM]
    __shared__ float sq[32][HDIM];
    __shared__ float sp[32][32];

    const int bh = blockIdx.y;
    const int b = bh / NHEAD;
    const int h = bh % NHEAD;
    const int q0 = blockIdx.x * QB;
    int n_str = (q0 + QB - 1) / STRIDE_ + 1;
    if (n_str > KMAX) n_str = KMAX;
    const int n_pad = (n_str + 31) & ~31;

    const int tid = threadIdx.x;

    for (int idx = tid; idx < n_str * 16; idx += 512) {
        const int t = idx >> 4;
        const int d4 = (idx & 15) * 4;
        const int j = t * STRIDE_;
        const float* kb = qkv + ((size_t)(b * SEQ + j)) * (3 * DMODEL) + h * HDIM;
        float4 kv = *(const float4*)(kb + DMODEL + d4);
        float4 vv = *(const float4*)(kb + 2 * DMODEL + d4);
        kT[(d4 + 0) * KPAD + t] = kv.x;
        kT[(d4 + 1) * KPAD + t] = kv.y;
        kT[(d4 + 2) * KPAD + t] = kv.z;
        kT[(d4 + 3) * KPAD + t] = kv.w;
        *(float4*)&vS[t * HDIM + d4] = vv;
    }
    for (int idx = tid; idx < (n_pad - n_str) * 16; idx += 512) {
        const int t = n_str + (idx >> 4);
        const int d4 = (idx & 15) * 4;
        *(float4*)&vS[t * HDIM + d4] = make_float4(0.f, 0.f, 0.f, 0.f);
        kT[(d4 + 0) * KPAD + t] = 0.f;
        kT[(d4 + 1) * KPAD + t] = 0.f;
        kT[(d4 + 2) * KPAD + t] = 0.f;
        kT[(d4 + 3) * KPAD + t] = 0.f;
    }
    __syncthreads();

    const int w = tid >> 5;
    const int lane = tid & 31;
    const float scale = 0.125f;

    for (int pass = 0; pass < 4; ++pass) {
        const int ia = q0 + pass * 32 + w;
        const int ib = ia + 16;
        const size_t qba = (size_t)(b * SEQ + ia) * (3 * DMODEL) + h * HDIM;
        const size_t qbb = (size_t)(b * SEQ + ib) * (3 * DMODEL) + h * HDIM;
        const float qa0 = qkv[qba + lane], qa1 = qkv[qba + lane + 32];
        const float qb0 = qkv[qbb + lane], qb1 = qkv[qbb + lane + 32];
        sq[w][lane] = qa0;       sq[w][lane + 32] = qa1;
        sq[w + 16][lane] = qb0;  sq[w + 16][lane + 32] = qb1;
        __syncwarp();

        const int n_a = ia / STRIDE_ + 1;
        const int n_b = ib / STRIDE_ + 1;
        float ma = -1e30f, mb = -1e30f, la = 0.f, lb = 0.f;
        float oa0 = 0.f, oa1 = 0.f, ob0 = 0.f, ob1 = 0.f;

        for (int t0 = 0; t0 < n_b; t0 += 32) {
            const int t = t0 + lane;
            float da = 0.f, db = 0.f;
            #pragma unroll
            for (int d = 0; d < HDIM; d += 4) {
                const float4 a4 = *(const float4*)&sq[w][d];
                const float4 b4 = *(const float4*)&sq[w + 16][d];
                const float k0 = kT[(d + 0) * KPAD + t];
                const float k1 = kT[(d + 1) * KPAD + t];
                const float k2 = kT[(d + 2) * KPAD + t];
                const float k3 = kT[(d + 3) * KPAD + t];
                da += a4.x * k0 + a4.y * k1 + a4.z * k2 + a4.w * k3;
                db += b4.x * k0 + b4.y * k1 + b4.z * k2 + b4.w * k3;
            }
            const float sa = (t < n_a) ? da * scale : -1e30f;
            const float sb = (t < n_b) ? db * scale : -1e30f;

            float mxa = sa, mxb = sb;
            #pragma unroll
            for (int off = 16; off; off >>= 1) {
                mxa = fmaxf(mxa, __shfl_xor_sync(0xFFFFFFFFu, mxa, off));
                mxb = fmaxf(mxb, __shfl_xor_sync(0xFFFFFFFFu, mxb, off));
            }
            const float mna = fmaxf(ma, mxa);
            const float mnb = fmaxf(mb, mxb);
            const float ala = __expf(ma - mna);
            const float alb = __expf(mb - mnb);
            float pa = __expf(sa - mna);
            float pb = __expf(sb - mnb);
            float sua = pa, sub = pb;
            #pragma unroll
            for (int off = 16; off; off >>= 1) {
                sua += __shfl_xor_sync(0xFFFFFFFFu, sua, off);
                sub += __shfl_xor_sync(0xFFFFFFFFu, sub, off);
            }
            la = la * ala + sua;
            lb = lb * alb + sub;
            ma = mna;
            mb = mnb;

            sp[w][lane] = pa;
            sp[w + 16][lane] = pb;
            __syncwarp();

            float a0 = 0.f, a1 = 0.f, b0 = 0.f, b1 = 0.f;
            const float* vb = &vS[(size_t)t0 * HDIM + 2 * lane];
            #pragma unroll
            for (int j4 = 0; j4 < 32; j4 += 4) {
                const float4 p4a = *(const float4*)&sp[w][j4];
                const float4 p4b = *(const float4*)&sp[w + 16][j4];
                const float2 v0 = *(const float2*)&vb[(j4 + 0) * HDIM];
                const float2 v1 = *(const float2*)&vb[(j4 + 1) * HDIM];
                const float2 v2 = *(const float2*)&vb[(j4 + 2) * HDIM];
                const float2 v3 = *(const float2*)&vb[(j4 + 3) * HDIM];
                a0 += p4a.x * v0.x + p4a.y * v1.x + p4a.z * v2.x + p4a.w * v3.x;
                a1 += p4a.x * v0.y + p4a.y * v1.y + p4a.z * v2.y + p4a.w * v3.y;
                b0 += p4b.x * v0.x + p4b.y * v1.x + p4b.z * v2.x + p4b.w * v3.x;
                b1 += p4b.x * v0.y + p4b.y * v1.y + p4b.z * v2.y + p4b.w * v3.y;
            }
            oa0 = oa0 * ala + a0;
            oa1 = oa1 * ala + a1;
            ob0 = ob0 * alb + b0;
            ob1 = ob1 * alb + b1;
            __syncwarp();
        }

        #pragma unroll
        for (int sel = 0; sel < 2; ++sel) {
            const int i = sel ? ib : ia;
            const float q0r = sel ? qb0 : qa0;
            const float q1r = sel ? qb1 : qa1;
            float& m_ = sel ? mb : ma;
            float& l_ = sel ? lb : la;
            float& x0 = sel ? ob0 : oa0;
            float& x1 = sel ? ob1 : oa1;
            #pragma unroll
            for (int e = 0; e < 2; e++) {
                const int j = i - e;
                if (j >= 0 && (j & 7) != 0) {
                    const size_t kb = (size_t)(b * SEQ + j) * (3 * DMODEL) + h * HDIM;
                    float part = q0r * qkv[kb + DMODEL + lane] + q1r * qkv[kb + DMODEL + lane + 32];
                    #pragma unroll
                    for (int off = 16; off; off >>= 1)
                        part += __shfl_xor_sync(0xFFFFFFFFu, part, off);
                    const float s = part * scale;
                    const float mn = fmaxf(m_, s);
                    const float al = __expf(m_ - mn);
                    const float p = __expf(s - mn);
                    const float2 vv = *(const float2*)&qkv[kb + 2 * DMODEL + 2 * lane];
                    l_ = l_ * al + p;
                    x0 = x0 * al + p * vv.x;
                    x1 = x1 * al + p * vv.y;
                    m_ = mn;
                }
            }
        }

        {
            const float iva = 1.f / la, ivb = 1.f / lb;
            const float fa0 = oa0 * iva, fa1 = oa1 * iva;
            const float fb0 = ob0 * ivb, fb1 = ob1 * ivb;
            const size_t oba = (size_t)(b * SEQ + ia) * DMODEL + h * HDIM + 2 * lane;
            const size_t obb = (size_t)(b * SEQ + ib) * DMODEL + h * HDIM + 2 * lane;
            __nv_bfloat16 h0 = __float2bfloat16(fa0), h1 = __float2bfloat16(fa1);
            *(__nv_bfloat162*)&oh[oba] = __nv_bfloat162(h0, h1);
            *(__nv_bfloat162*)&ol[oba] = __nv_bfloat162(
                __float2bfloat16(fa0 - __bfloat162float(h0)),
                __float2bfloat16(fa1 - __bfloat162float(h1)));
            h0 = __float2bfloat16(fb0); h1 = __float2bfloat16(fb1);
            *(__nv_bfloat162*)&oh[obb] = __nv_bfloat162(h0, h1);
            *(__nv_bfloat162*)&ol[obb] = __nv_bfloat162(
                __float2bfloat16(fb0 - __bfloat162float(h0)),
                __float2bfloat16(fb1 - __bfloat162float(h1)));
        }
        __syncwarp();
    }
}

// ---------------- launcher ----------------
extern "C" void kernel_launch(void* const* d_in, const int* in_sizes, int n_in,
                              void* d_out, int out_size)
{
    const float* x      = (const float*)d_in[0];
    const float* qkv_w  = (const float*)d_in[1];
    const float* qkv_b  = (const float*)d_in[2];
    const float* out_w  = (const float*)d_in[3];
    const float* out_b  = (const float*)d_in[4];
    float* out = (float*)d_out;

    float* qkv; cudaGetSymbolAddress((void**)&qkv, g_qkv);
    __nv_bfloat16 *ah, *al, *bh, *bl, *owh, *owl, *xh, *xl;
    cudaGetSymbolAddress((void**)&ah,  g_ah);
    cudaGetSymbolAddress((void**)&al,  g_al);
    cudaGetSymbolAddress((void**)&bh,  g_bh);
    cudaGetSymbolAddress((void**)&bl,  g_bl);
    cudaGetSymbolAddress((void**)&owh, g_owh);
    cudaGetSymbolAddress((void**)&owl, g_owl);
    cudaGetSymbolAddress((void**)&xh,  g_xh);
    cudaGetSymbolAddress((void**)&xl,  g_xl);

    cudaFuncSetAttribute(gemm_mma256_kernel, cudaFuncAttributeMaxDynamicSharedMemorySize, GEMM2_SMEM);
    cudaFuncSetAttribute(gemm_mma_kernel, cudaFuncAttributeMaxDynamicSharedMemorySize, GEMM_SMEM);
    const int attn_smem = (HDIM * KPAD + KMAX * HDIM) * sizeof(float);
    cudaFuncSetAttribute(attn_kernel, cudaFuncAttributeMaxDynamicSharedMemorySize, attn_smem);

    // hi/lo splits of x and weights
    {
        int n4 = M_TOTAL * K_DIM / 4;
        conv_hilo_kernel<<<(n4 + 255) / 256, 256>>>(x, xh, xl, n4);
        n4 = N_QKV * K_DIM / 4;
        conv_hilo_kernel<<<(n4 + 255) / 256, 256>>>(qkv_w, bh, bl, n4);
        n4 = DMODEL * K_DIM / 4;
        conv_hilo_kernel<<<(n4 + 255) / 256, 256>>>(out_w, owh, owl, n4);
    }

    // 1) QKV projection: 256x128 tiles, 288 CTAs (~2 waves)
    gemm_mma256_kernel<<<dim3(N_QKV / 128, M_TOTAL / 256), 256, GEMM2_SMEM>>>(
        xh, xl, bh, bl, qkv_b, qkv, N_QKV);

    // 2) strided attention (writes bf16 hi/lo directly)
    attn_kernel<<<dim3(SEQ / QB, BATCH * NHEAD), 512, attn_smem>>>(qkv, ah, al);

    // 3) output projection: 128x128 tiles (192 CTAs)
    gemm_mma_kernel<<<dim3(DMODEL / 128, M_TOTAL / 128), 256, GEMM_SMEM>>>(
        ah, al, owh, owl, out_b, out, DMODEL);
}

// round 6
// speedup vs baseline: 2.2835x; 1.0193x over previous
#include <cuda_runtime.h>
#include <cuda_bf16.h>
#include <cstdint>

// ---------------- problem constants ----------------
#define BATCH 2
#define SEQ   2048
#define DMODEL 768
#define NHEAD 12
#define HDIM  64
#define STRIDE_ 8
#define QB    128
#define KMAX  (SEQ/STRIDE_)   // 256
#define KPAD  257

#define M_TOTAL (BATCH*SEQ)   // 4096
#define K_DIM   DMODEL        // 768
#define N_QKV   (3*DMODEL)    // 2304

// ---------------- device scratch ----------------
__device__ float g_qkv[M_TOTAL * N_QKV];
__device__ __nv_bfloat16 g_ah[M_TOTAL * K_DIM];
__device__ __nv_bfloat16 g_al[M_TOTAL * K_DIM];
__device__ __nv_bfloat16 g_bh[N_QKV * K_DIM];
__device__ __nv_bfloat16 g_bl[N_QKV * K_DIM];
__device__ __nv_bfloat16 g_owh[DMODEL * K_DIM];
__device__ __nv_bfloat16 g_owl[DMODEL * K_DIM];
__device__ __nv_bfloat16 g_xh[M_TOTAL * K_DIM];
__device__ __nv_bfloat16 g_xl[M_TOTAL * K_DIM];

// ---------------- PTX helpers (portable: sm_80+) ----------------
__device__ __forceinline__ uint32_t smem_u32(const void* p) {
    uint32_t a;
    asm("{ .reg .u64 t; cvta.to.shared.u64 t, %1; cvt.u32.u64 %0, t; }" : "=r"(a) : "l"(p));
    return a;
}

#define CP_ASYNC16(dst, src) \
    asm volatile("cp.async.cg.shared.global [%0], [%1], 16;" :: "r"(dst), "l"(src))
#define CP_COMMIT() asm volatile("cp.async.commit_group;" ::: "memory")
#define CP_WAIT1() asm volatile("cp.async.wait_group 1;" ::: "memory")
#define CP_WAIT0() asm volatile("cp.async.wait_group 0;" ::: "memory")

#define LDSM_X4(r0, r1, r2, r3, addr) \
    asm volatile("ldmatrix.sync.aligned.m8n8.x4.shared.b16 {%0,%1,%2,%3}, [%4];" \
        : "=r"(r0), "=r"(r1), "=r"(r2), "=r"(r3) : "r"(addr))

#define MMA_BF16(c, a, b) \
    asm volatile("mma.sync.aligned.m16n8k16.row.col.f32.bf16.bf16.f32 " \
        "{%0,%1,%2,%3}, {%4,%5,%6,%7}, {%8,%9}, {%0,%1,%2,%3};" \
        : "+f"((c)[0]), "+f"((c)[1]), "+f"((c)[2]), "+f"((c)[3]) \
        : "r"((a)[0]), "r"((a)[1]), "r"((a)[2]), "r"((a)[3]), \
          "r"((b)[0]), "r"((b)[1]))

// ---------------- fp32 -> bf16 hi/lo split ----------------
__global__ __launch_bounds__(256)
void conv_hilo_kernel(const float* __restrict__ in, __nv_bfloat16* __restrict__ hi,
                      __nv_bfloat16* __restrict__ lo, int n4)
{
    int i = blockIdx.x * 256 + threadIdx.x;
    if (i >= n4) return;
    float4 v = ((const float4*)in)[i];
    __nv_bfloat16 h0 = __float2bfloat16(v.x);
    __nv_bfloat16 h1 = __float2bfloat16(v.y);
    __nv_bfloat16 h2 = __float2bfloat16(v.z);
    __nv_bfloat16 h3 = __float2bfloat16(v.w);
    __nv_bfloat16 l0 = __float2bfloat16(v.x - __bfloat162float(h0));
    __nv_bfloat16 l1 = __float2bfloat16(v.y - __bfloat162float(h1));
    __nv_bfloat16 l2 = __float2bfloat16(v.z - __bfloat162float(h2));
    __nv_bfloat16 l3 = __float2bfloat16(v.w - __bfloat162float(h3));
    __nv_bfloat162* hp = (__nv_bfloat162*)hi;
    __nv_bfloat162* lp = (__nv_bfloat162*)lo;
    hp[2*i]   = __nv_bfloat162(h0, h1);
    hp[2*i+1] = __nv_bfloat162(h2, h3);
    lp[2*i]   = __nv_bfloat162(l0, l1);
    lp[2*i+1] = __nv_bfloat162(l2, l3);
}

// ---------------- mma.sync GEMM: 128x128, 2-stage, 2 CTAs/SM ----------------
#define GBK 32
#define NCHUNK (K_DIM / GBK)          // 24
#define TPAD 40
#define TILE_BYTES (128 * TPAD * 2)   // 10240
#define STAGE_BYTES (4 * TILE_BYTES)  // 40960
#define GEMM_SMEM (2 * STAGE_BYTES)   // 81920 -> 2 CTAs/SM

__global__ __launch_bounds__(256, 2)
void gemm_mma_kernel(const __nv_bfloat16* __restrict__ Ah, const __nv_bfloat16* __restrict__ Al,
                     const __nv_bfloat16* __restrict__ Bh, const __nv_bfloat16* __restrict__ Bl,
                     const float* __restrict__ bias, float* __restrict__ C, int N)
{
    extern __shared__ char dsm[];
    const uint32_t sbase = smem_u32(dsm);
    const int tid = threadIdx.x;
    const int lane = tid & 31;
    const int wid = tid >> 5;
    const int wm = (wid & 1) * 64;
    const int wn = (wid >> 1) * 32;
    const int bm = blockIdx.y * 128;
    const int bn = blockIdx.x * 128;

    const __nv_bfloat16* gp[4] = { Ah, Al, Bh, Bl };

    float acc[4][4][4];
    #pragma unroll
    for (int i = 0; i < 4; i++)
        #pragma unroll
        for (int j = 0; j < 4; j++)
            #pragma unroll
            for (int r = 0; r < 4; r++) acc[i][j][r] = 0.f;

    auto issue = [&](int stage, int kc) {
        const uint32_t st = sbase + (uint32_t)stage * STAGE_BYTES;
        #pragma unroll
        for (int t = 0; t < 8; ++t) {
            int task = tid + t * 256;
            int tile = task >> 9;
            int idx  = task & 511;
            int r = idx >> 2, q = idx & 3;
            int row = (tile < 2 ? bm : bn) + r;
            uint32_t dst = st + (uint32_t)tile * TILE_BYTES + (uint32_t)(r * TPAD + q * 8) * 2;
            CP_ASYNC16(dst, gp[tile] + (size_t)row * K_DIM + kc + q * 8);
        }
        CP_COMMIT();
    };

    issue(0, 0);
    issue(1, GBK);

    const int g = lane >> 3;
    const int arow = wm + (g & 1) * 8 + (lane & 7);
    const int acoff = (g >> 1) * 8;
    const int brow0 = wn + (g >> 1) * 8 + (lane & 7);
    const int bcoff = (g & 1) * 8;

    for (int c = 0; c < NCHUNK; ++c) {
        if (c + 1 < NCHUNK) { CP_WAIT1(); } else { CP_WAIT0(); }
        __syncthreads();

        const uint32_t st = sbase + (uint32_t)(c & 1) * STAGE_BYTES;
        const uint32_t aH = st;
        const uint32_t aL = st + TILE_BYTES;
        const uint32_t bH = st + 2 * TILE_BYTES;
        const uint32_t bL = st + 3 * TILE_BYTES;

        #pragma unroll
        for (int ks = 0; ks < 2; ++ks) {
            const int acol = ks * 16 + acoff;
            const int bcol = ks * 16 + bcoff;
            uint32_t ah[4][4], al[4][4];
            #pragma unroll
            for (int mf = 0; mf < 4; ++mf) {
                uint32_t off = (uint32_t)((arow + mf * 16) * TPAD + acol) * 2;
                LDSM_X4(ah[mf][0], ah[mf][1], ah[mf][2], ah[mf][3], aH + off);
                LDSM_X4(al[mf][0], al[mf][1], al[mf][2], al[mf][3], aL + off);
            }
            #pragma unroll
            for (int nf2 = 0; nf2 < 2; ++nf2) {
                uint32_t off = (uint32_t)((brow0 + nf2 * 16) * TPAD + bcol) * 2;
                uint32_t bh[2][2], bl[2][2];
                LDSM_X4(bh[0][0], bh[0][1], bh[1][0], bh[1][1], bH + off);
                LDSM_X4(bl[0][0], bl[0][1], bl[1][0], bl[1][1], bL + off);
                #pragma unroll
                for (int mf = 0; mf < 4; ++mf) {
                    #pragma unroll
                    for (int q = 0; q < 2; ++q) {
                        float* a4 = acc[mf][2 * nf2 + q];
                        MMA_BF16(a4, ah[mf], bh[q]);
                        MMA_BF16(a4, ah[mf], bl[q]);
                        MMA_BF16(a4, al[mf], bh[q]);
                    }
                }
            }
        }
        __syncthreads();
        if (c + 2 < NCHUNK) issue(c & 1, (c + 2) * GBK);
    }

    #pragma unroll
    for (int mf = 0; mf < 4; ++mf) {
        const int m = bm + wm + mf * 16 + (lane >> 2);
        #pragma unroll
        for (int nf = 0; nf < 4; ++nf) {
            const int n = bn + wn + nf * 8 + (lane & 3) * 2;
            const float2 bv = *(const float2*)&bias[n];
            float2 v0 = { acc[mf][nf][0] + bv.x, acc[mf][nf][1] + bv.y };
            float2 v1 = { acc[mf][nf][2] + bv.x, acc[mf][nf][3] + bv.y };
            *(float2*)&C[(size_t)m * N + n]       = v0;
            *(float2*)&C[(size_t)(m + 8) * N + n] = v1;
        }
    }
}

// ---------------- strided attention: 2 queries/warp, vectorized -------------
__global__ __launch_bounds__(512, 1)
void attn_kernel(const float* __restrict__ qkv,
                 __nv_bfloat16* __restrict__ oh, __nv_bfloat16* __restrict__ ol)
{
    extern __shared__ float smf[];
    float* kT = smf;                    // [HDIM][KPAD]
    float* vS = smf + HDIM * KPAD;      // [n_pad][HDIM]
    __shared__ float sq[32][HDIM];
    __shared__ float sp[32][32];

    const int bh = blockIdx.y;
    const int b = bh / NHEAD;
    const int h = bh % NHEAD;
    const int q0 = blockIdx.x * QB;
    int n_str = (q0 + QB - 1) / STRIDE_ + 1;
    if (n_str > KMAX) n_str = KMAX;
    const int n_pad = (n_str + 31) & ~31;

    const int tid = threadIdx.x;

    for (int idx = tid; idx < n_str * 16; idx += 512) {
        const int t = idx >> 4;
        const int d4 = (idx & 15) * 4;
        const int j = t * STRIDE_;
        const float* kb = qkv + ((size_t)(b * SEQ + j)) * (3 * DMODEL) + h * HDIM;
        float4 kv = *(const float4*)(kb + DMODEL + d4);
        float4 vv = *(const float4*)(kb + 2 * DMODEL + d4);
        kT[(d4 + 0) * KPAD + t] = kv.x;
        kT[(d4 + 1) * KPAD + t] = kv.y;
        kT[(d4 + 2) * KPAD + t] = kv.z;
        kT[(d4 + 3) * KPAD + t] = kv.w;
        *(float4*)&vS[t * HDIM + d4] = vv;
    }
    for (int idx = tid; idx < (n_pad - n_str) * 16; idx += 512) {
        const int t = n_str + (idx >> 4);
        const int d4 = (idx & 15) * 4;
        *(float4*)&vS[t * HDIM + d4] = make_float4(0.f, 0.f, 0.f, 0.f);
        kT[(d4 + 0) * KPAD + t] = 0.f;
        kT[(d4 + 1) * KPAD + t] = 0.f;
        kT[(d4 + 2) * KPAD + t] = 0.f;
        kT[(d4 + 3) * KPAD + t] = 0.f;
    }
    __syncthreads();

    const int w = tid >> 5;
    const int lane = tid & 31;
    const float scale = 0.125f;

    for (int pass = 0; pass < 4; ++pass) {
        const int ia = q0 + pass * 32 + w;
        const int ib = ia + 16;
        const size_t qba = (size_t)(b * SEQ + ia) * (3 * DMODEL) + h * HDIM;
        const size_t qbb = (size_t)(b * SEQ + ib) * (3 * DMODEL) + h * HDIM;
        const float qa0 = qkv[qba + lane], qa1 = qkv[qba + lane + 32];
        const float qb0 = qkv[qbb + lane], qb1 = qkv[qbb + lane + 32];
        sq[w][lane] = qa0;       sq[w][lane + 32] = qa1;
        sq[w + 16][lane] = qb0;  sq[w + 16][lane + 32] = qb1;
        __syncwarp();

        const int n_a = ia / STRIDE_ + 1;
        const int n_b = ib / STRIDE_ + 1;
        float ma = -1e30f, mb = -1e30f, la = 0.f, lb = 0.f;
        float oa0 = 0.f, oa1 = 0.f, ob0 = 0.f, ob1 = 0.f;

        for (int t0 = 0; t0 < n_b; t0 += 32) {
            const int t = t0 + lane;
            float da = 0.f, db = 0.f;
            #pragma unroll
            for (int d = 0; d < HDIM; d += 4) {
                const float4 a4 = *(const float4*)&sq[w][d];
                const float4 b4 = *(const float4*)&sq[w + 16][d];
                const float k0 = kT[(d + 0) * KPAD + t];
                const float k1 = kT[(d + 1) * KPAD + t];
                const float k2 = kT[(d + 2) * KPAD + t];
                const float k3 = kT[(d + 3) * KPAD + t];
                da += a4.x * k0 + a4.y * k1 + a4.z * k2 + a4.w * k3;
                db += b4.x * k0 + b4.y * k1 + b4.z * k2 + b4.w * k3;
            }
            const float sa = (t < n_a) ? da * scale : -1e30f;
            const float sb = (t < n_b) ? db * scale : -1e30f;

            float mxa = sa, mxb = sb;
            #pragma unroll
            for (int off = 16; off; off >>= 1) {
                mxa = fmaxf(mxa, __shfl_xor_sync(0xFFFFFFFFu, mxa, off));
                mxb = fmaxf(mxb, __shfl_xor_sync(0xFFFFFFFFu, mxb, off));
            }
            const float mna = fmaxf(ma, mxa);
            const float mnb = fmaxf(mb, mxb);
            const float ala = __expf(ma - mna);
            const float alb = __expf(mb - mnb);
            float pa = __expf(sa - mna);
            float pb = __expf(sb - mnb);
            float sua = pa, sub = pb;
            #pragma unroll
            for (int off = 16; off; off >>= 1) {
                sua += __shfl_xor_sync(0xFFFFFFFFu, sua, off);
                sub += __shfl_xor_sync(0xFFFFFFFFu, sub, off);
            }
            la = la * ala + sua;
            lb = lb * alb + sub;
            ma = mna;
            mb = mnb;

            sp[w][lane] = pa;
            sp[w + 16][lane] = pb;
            __syncwarp();

            float a0 = 0.f, a1 = 0.f, b0 = 0.f, b1 = 0.f;
            const float* vb = &vS[(size_t)t0 * HDIM + 2 * lane];
            #pragma unroll
            for (int j4 = 0; j4 < 32; j4 += 4) {
                const float4 p4a = *(const float4*)&sp[w][j4];
                const float4 p4b = *(const float4*)&sp[w + 16][j4];
                const float2 v0 = *(const float2*)&vb[(j4 + 0) * HDIM];
                const float2 v1 = *(const float2*)&vb[(j4 + 1) * HDIM];
                const float2 v2 = *(const float2*)&vb[(j4 + 2) * HDIM];
                const float2 v3 = *(const float2*)&vb[(j4 + 3) * HDIM];
                a0 += p4a.x * v0.x + p4a.y * v1.x + p4a.z * v2.x + p4a.w * v3.x;
                a1 += p4a.x * v0.y + p4a.y * v1.y + p4a.z * v2.y + p4a.w * v3.y;
                b0 += p4b.x * v0.x + p4b.y * v1.x + p4b.z * v2.x + p4b.w * v3.x;
                b1 += p4b.x * v0.y + p4b.y * v1.y + p4b.z * v2.y + p4b.w * v3.y;
            }
            oa0 = oa0 * ala + a0;
            oa1 = oa1 * ala + a1;
            ob0 = ob0 * alb + b0;
            ob1 = ob1 * alb + b1;
            __syncwarp();
        }

        #pragma unroll
        for (int sel = 0; sel < 2; ++sel) {
            const int i = sel ? ib : ia;
            const float q0r = sel ? qb0 : qa0;
            const float q1r = sel ? qb1 : qa1;
            float& m_ = sel ? mb : ma;
            float& l_ = sel ? lb : la;
            float& x0 = sel ? ob0 : oa0;
            float& x1 = sel ? ob1 : oa1;
            #pragma unroll
            for (int e = 0; e < 2; e++) {
                const int j = i - e;
                if (j >= 0 && (j & 7) != 0) {
                    const size_t kb = (size_t)(b * SEQ + j) * (3 * DMODEL) + h * HDIM;
                    float part = q0r * qkv[kb + DMODEL + lane] + q1r * qkv[kb + DMODEL + lane + 32];
                    #pragma unroll
                    for (int off = 16; off; off >>= 1)
                        part += __shfl_xor_sync(0xFFFFFFFFu, part, off);
                    const float s = part * scale;
                    const float mn = fmaxf(m_, s);
                    const float al = __expf(m_ - mn);
                    const float p = __expf(s - mn);
                    const float2 vv = *(const float2*)&qkv[kb + 2 * DMODEL + 2 * lane];
                    l_ = l_ * al + p;
                    x0 = x0 * al + p * vv.x;
                    x1 = x1 * al + p * vv.y;
                    m_ = mn;
                }
            }
        }

        {
            const float iva = 1.f / la, ivb = 1.f / lb;
            const float fa0 = oa0 * iva, fa1 = oa1 * iva;
            const float fb0 = ob0 * ivb, fb1 = ob1 * ivb;
            const size_t oba = (size_t)(b * SEQ + ia) * DMODEL + h * HDIM + 2 * lane;
            const size_t obb = (size_t)(b * SEQ + ib) * DMODEL + h * HDIM + 2 * lane;
            __nv_bfloat16 h0 = __float2bfloat16(fa0), h1 = __float2bfloat16(fa1);
            *(__nv_bfloat162*)&oh[oba] = __nv_bfloat162(h0, h1);
            *(__nv_bfloat162*)&ol[oba] = __nv_bfloat162(
                __float2bfloat16(fa0 - __bfloat162float(h0)),
                __float2bfloat16(fa1 - __bfloat162float(h1)));
            h0 = __float2bfloat16(fb0); h1 = __float2bfloat16(fb1);
            *(__nv_bfloat162*)&oh[obb] = __nv_bfloat162(h0, h1);
            *(__nv_bfloat162*)&ol[obb] = __nv_bfloat162(
                __float2bfloat16(fb0 - __bfloat162float(h0)),
                __float2bfloat16(fb1 - __bfloat162float(h1)));
        }
        __syncwarp();
    }
}

// ---------------- launcher ----------------
extern "C" void kernel_launch(void* const* d_in, const int* in_sizes, int n_in,
                              void* d_out, int out_size)
{
    const float* x      = (const float*)d_in[0];
    const float* qkv_w  = (const float*)d_in[1];
    const float* qkv_b  = (const float*)d_in[2];
    const float* out_w  = (const float*)d_in[3];
    const float* out_b  = (const float*)d_in[4];
    float* out = (float*)d_out;

    float* qkv; cudaGetSymbolAddress((void**)&qkv, g_qkv);
    __nv_bfloat16 *ah, *al, *bh, *bl, *owh, *owl, *xh, *xl;
    cudaGetSymbolAddress((void**)&ah,  g_ah);
    cudaGetSymbolAddress((void**)&al,  g_al);
    cudaGetSymbolAddress((void**)&bh,  g_bh);
    cudaGetSymbolAddress((void**)&bl,  g_bl);
    cudaGetSymbolAddress((void**)&owh, g_owh);
    cudaGetSymbolAddress((void**)&owl, g_owl);
    cudaGetSymbolAddress((void**)&xh,  g_xh);
    cudaGetSymbolAddress((void**)&xl,  g_xl);

    cudaFuncSetAttribute(gemm_mma_kernel, cudaFuncAttributeMaxDynamicSharedMemorySize, GEMM_SMEM);
    const int attn_smem = (HDIM * KPAD + KMAX * HDIM) * sizeof(float);
    cudaFuncSetAttribute(attn_kernel, cudaFuncAttributeMaxDynamicSharedMemorySize, attn_smem);

    // hi/lo splits of x and weights
    {
        int n4 = M_TOTAL * K_DIM / 4;
        conv_hilo_kernel<<<(n4 + 255) / 256, 256>>>(x, xh, xl, n4);
        n4 = N_QKV * K_DIM / 4;
        conv_hilo_kernel<<<(n4 + 255) / 256, 256>>>(qkv_w, bh, bl, n4);
        n4 = DMODEL * K_DIM / 4;
        conv_hilo_kernel<<<(n4 + 255) / 256, 256>>>(out_w, owh, owl, n4);
    }

    // 1) QKV projection: 576 CTAs, 2 CTAs/SM
    gemm_mma_kernel<<<dim3(N_QKV / 128, M_TOTAL / 128), 256, GEMM_SMEM>>>(
        xh, xl, bh, bl, qkv_b, qkv, N_QKV);

    // 2) strided attention (writes bf16 hi/lo directly)
    attn_kernel<<<dim3(SEQ / QB, BATCH * NHEAD), 512, attn_smem>>>(qkv, ah, al);

    // 3) output projection: 192 CTAs
    gemm_mma_kernel<<<dim3(DMODEL / 128, M_TOTAL / 128), 256, GEMM_SMEM>>>(
        ah, al, owh, owl, out_b, out, DMODEL);
}